// round 12
// baseline (speedup 1.0000x reference)
#include <cuda_runtime.h>
#include <cuda_bf16.h>
#include <math.h>

#define Bc 2
#define Cdim 256
#define NTc 2304
#define KDc 256
#define CLSc 20
#define Nc 2324
#define NcP 2336
#define HDSc 8
#define HDc 32
#define SCALEc 0.17677669529663687f
#define EPSc 1e-5f
#define MRc 0.3f

// ---------------- device scratch ----------------
__device__ float g_xqt[Bc*NTc*Cdim];
__device__ float g_qin[Bc*NTc*Cdim];
__device__ float g_kin[Bc*Nc*KDc];
__device__ __nv_bfloat16 g_qh[Bc*HDSc*NTc*HDc];   // q*SCALE, (bh, m, d) bf16
__device__ __nv_bfloat16 g_kh[Bc*HDSc*Nc*HDc];    // k (bh, n, d) bf16
__device__ __nv_bfloat16 g_vt[Bc*HDSc*HDc*NcP];   // v transposed (bh, d, n) bf16 (pad cols 0)
__device__ float g_xattn[Bc*NTc*Cdim];
__device__ float g_xres [Bc*NTc*Cdim];
__device__ float g_xln  [Bc*NTc*Cdim];
__device__ float g_hbuf [Bc*NTc*4*Cdim];

__device__ __forceinline__ void mma16816(float* c, const unsigned* a, const unsigned* b){
    asm volatile(
        "mma.sync.aligned.m16n8k16.row.col.f32.bf16.bf16.f32 "
        "{%0,%1,%2,%3}, {%4,%5,%6,%7}, {%8,%9}, {%0,%1,%2,%3};\n"
        : "+f"(c[0]), "+f"(c[1]), "+f"(c[2]), "+f"(c[3])
        : "r"(a[0]), "r"(a[1]), "r"(a[2]), "r"(a[3]), "r"(b[0]), "r"(b[1]));
}
__device__ __forceinline__ void mma1688_tf32(float* c, const unsigned* a, const unsigned* b){
    asm volatile(
        "mma.sync.aligned.m16n8k8.row.col.f32.tf32.tf32.f32 "
        "{%0,%1,%2,%3}, {%4,%5,%6,%7}, {%8,%9}, {%0,%1,%2,%3};\n"
        : "+f"(c[0]), "+f"(c[1]), "+f"(c[2]), "+f"(c[3])
        : "r"(a[0]), "r"(a[1]), "r"(a[2]), "r"(a[3]), "r"(b[0]), "r"(b[1]));
}
__device__ __forceinline__ unsigned f2tf32(float x){
    unsigned r;
    asm("cvt.rna.tf32.f32 %0, %1;" : "=r"(r) : "f"(x));
    return r;
}
__device__ __forceinline__ unsigned packbf(float lo, float hi){
    __nv_bfloat162 t = __floats2bfloat162_rn(lo, hi);
    return *(unsigned*)&t;
}

// ---------------- LN over transposed x_query ----------
__global__ __launch_bounds__(256) void ln_q_kernel(
    const float* __restrict__ xq, const float* __restrict__ g,
    const float* __restrict__ be, float* __restrict__ out_raw,
    float* __restrict__ out_ln)
{
    __shared__ float tile[256][33];
    __shared__ float redS[8][32], redQ[8][32];
    __shared__ float s_mean[32], s_rstd[32];
    int b = blockIdx.y;
    int p0 = blockIdx.x * 32;
    int t = threadIdx.x;
    int pl = t & 31, grp = t >> 5;
    const float* src = xq + (size_t)b*Cdim*NTc + p0 + pl;
#pragma unroll
    for (int cc = 0; cc < 32; cc++) {
        int c = cc*8 + grp;
        tile[c][pl] = src[(size_t)c*NTc];
    }
    __syncthreads();
    float s = 0.f, q = 0.f;
#pragma unroll
    for (int j = 0; j < 32; j++) {
        float v = tile[grp*32 + j][pl];
        s += v; q += v*v;
    }
    redS[grp][pl] = s; redQ[grp][pl] = q;
    __syncthreads();
    if (grp == 0) {
        float S = 0.f, Q = 0.f;
#pragma unroll
        for (int i = 0; i < 8; i++) { S += redS[i][pl]; Q += redQ[i][pl]; }
        float m = S * (1.f/256.f);
        float var = Q * (1.f/256.f) - m*m;
        s_mean[pl] = m;
        s_rstd[pl] = rsqrtf(var + EPSc);
    }
    __syncthreads();
    float gg = g[t], bb = be[t];
    for (int p = 0; p < 32; p++) {
        float v = tile[t][p];
        size_t o = ((size_t)b*NTc + p0 + p)*Cdim + t;
        out_raw[o] = v;
        out_ln[o]  = (v - s_mean[p]) * s_rstd[p] * gg + bb;
    }
}

// ---------------- row LN ----------------
__global__ __launch_bounds__(256) void ln_row_kernel(
    const float* __restrict__ x, const float* __restrict__ g,
    const float* __restrict__ be, float* __restrict__ y)
{
    int r = blockIdx.x;
    int t = threadIdx.x;
    float v = x[(size_t)r*256 + t];
    float s = v, q = v*v;
#pragma unroll
    for (int off = 16; off >= 1; off >>= 1) {
        s += __shfl_xor_sync(0xffffffffu, s, off);
        q += __shfl_xor_sync(0xffffffffu, q, off);
    }
    __shared__ float ss[8], sq[8];
    __shared__ float s_mean, s_rstd;
    int warp = t >> 5, lane = t & 31;
    if (lane == 0) { ss[warp] = s; sq[warp] = q; }
    __syncthreads();
    if (t == 0) {
        float S = 0.f, Q = 0.f;
#pragma unroll
        for (int i = 0; i < 8; i++) { S += ss[i]; Q += sq[i]; }
        float m = S * (1.f/256.f);
        float var = Q * (1.f/256.f) - m*m;
        s_mean = m;
        s_rstd = rsqrtf(var + EPSc);
    }
    __syncthreads();
    y[(size_t)r*256 + t] = (v - s_mean) * s_rstd * g[t] + be[t];
}

// ---------------- TF32 GEMM, BM=128 BN=64 BK=32, 2-stage pipeline ----------
__global__ __launch_bounds__(256) void sgemm_tc(
    const float* __restrict__ A, const float* __restrict__ Bw,
    int Mrows, int Ncols, int Kdim, int mode,
    const float* __restrict__ bias, const float* __restrict__ resid,
    float* __restrict__ out)
{
    __shared__ unsigned As[2][128][36];
    __shared__ unsigned Bs[2][32][68];

    int m0 = blockIdx.x * 128, n0 = blockIdx.y * 64;
    int t = threadIdx.x;
    int wid = t >> 5, lane = t & 31;
    int wm = wid & 3, wn = wid >> 2;
    int qr = lane >> 2, tig = lane & 3;

    float c[2][4][4];
#pragma unroll
    for (int mt = 0; mt < 2; mt++)
#pragma unroll
        for (int nt = 0; nt < 4; nt++)
#pragma unroll
            for (int e = 0; e < 4; e++) c[mt][nt][e] = 0.f;

    int ar = t >> 3, ac4 = (t & 7) * 4;
    int br = t >> 4, bc4 = (t & 15) * 4;
    int nit = Kdim >> 5;

    float4 aReg[4], bReg[2];
#pragma unroll
    for (int i = 0; i < 4; i++) {
        int row = ar + i*32;
        aReg[i] = make_float4(0.f,0.f,0.f,0.f);
        if (m0 + row < Mrows)
            aReg[i] = *(const float4*)&A[(size_t)(m0+row)*Kdim + ac4];
    }
#pragma unroll
    for (int i = 0; i < 2; i++)
        bReg[i] = *(const float4*)&Bw[(size_t)(br + i*16)*Ncols + n0 + bc4];
#pragma unroll
    for (int i = 0; i < 4; i++) {
        int row = ar + i*32;
        As[0][row][ac4+0] = f2tf32(aReg[i].x); As[0][row][ac4+1] = f2tf32(aReg[i].y);
        As[0][row][ac4+2] = f2tf32(aReg[i].z); As[0][row][ac4+3] = f2tf32(aReg[i].w);
    }
#pragma unroll
    for (int i = 0; i < 2; i++) {
        int row = br + i*16;
        Bs[0][row][bc4+0] = f2tf32(bReg[i].x); Bs[0][row][bc4+1] = f2tf32(bReg[i].y);
        Bs[0][row][bc4+2] = f2tf32(bReg[i].z); Bs[0][row][bc4+3] = f2tf32(bReg[i].w);
    }

    for (int it = 0; it < nit; it++) {
        __syncthreads();
        int cur = it & 1, nxt = cur ^ 1;
        if (it + 1 < nit) {
            int k0 = (it + 1) << 5;
#pragma unroll
            for (int i = 0; i < 4; i++) {
                int row = ar + i*32;
                aReg[i] = make_float4(0.f,0.f,0.f,0.f);
                if (m0 + row < Mrows)
                    aReg[i] = *(const float4*)&A[(size_t)(m0+row)*Kdim + k0 + ac4];
            }
#pragma unroll
            for (int i = 0; i < 2; i++)
                bReg[i] = *(const float4*)&Bw[(size_t)(k0 + br + i*16)*Ncols + n0 + bc4];
        }

#pragma unroll
        for (int kk = 0; kk < 32; kk += 8) {
            unsigned afr[2][4], bfr[4][2];
#pragma unroll
            for (int mt = 0; mt < 2; mt++) {
                int rb = wm*32 + mt*16;
                afr[mt][0] = As[cur][rb + qr    ][kk + tig];
                afr[mt][1] = As[cur][rb + qr + 8][kk + tig];
                afr[mt][2] = As[cur][rb + qr    ][kk + tig + 4];
                afr[mt][3] = As[cur][rb + qr + 8][kk + tig + 4];
            }
#pragma unroll
            for (int nt = 0; nt < 4; nt++) {
                int cb = wn*32 + nt*8 + qr;
                bfr[nt][0] = Bs[cur][kk + tig    ][cb];
                bfr[nt][1] = Bs[cur][kk + tig + 4][cb];
            }
#pragma unroll
            for (int mt = 0; mt < 2; mt++)
#pragma unroll
                for (int nt = 0; nt < 4; nt++)
                    mma1688_tf32(c[mt][nt], afr[mt], bfr[nt]);
        }

        if (it + 1 < nit) {
#pragma unroll
            for (int i = 0; i < 4; i++) {
                int row = ar + i*32;
                As[nxt][row][ac4+0] = f2tf32(aReg[i].x); As[nxt][row][ac4+1] = f2tf32(aReg[i].y);
                As[nxt][row][ac4+2] = f2tf32(aReg[i].z); As[nxt][row][ac4+3] = f2tf32(aReg[i].w);
            }
#pragma unroll
            for (int i = 0; i < 2; i++) {
                int row = br + i*16;
                Bs[nxt][row][bc4+0] = f2tf32(bReg[i].x); Bs[nxt][row][bc4+1] = f2tf32(bReg[i].y);
                Bs[nxt][row][bc4+2] = f2tf32(bReg[i].z); Bs[nxt][row][bc4+3] = f2tf32(bReg[i].w);
            }
        }
    }

#pragma unroll
    for (int mt = 0; mt < 2; mt++) {
#pragma unroll
        for (int ri = 0; ri < 2; ri++) {
            int r = m0 + wm*32 + mt*16 + qr + ri*8;
            if (r >= Mrows) continue;
#pragma unroll
            for (int nt = 0; nt < 4; nt++) {
#pragma unroll
                for (int e = 0; e < 2; e++) {
                    int cidx = n0 + wn*32 + nt*8 + tig*2 + e;
                    float v = c[mt][nt][ri*2 + e];
                    if (mode == 0) {
                        int b = r / NTc, ii = r % NTc;
                        int h = cidx >> 5, d = cidx & 31;
                        g_qh[(((size_t)b*HDSc + h)*NTc + ii)*HDc + d] = __float2bfloat16(v * SCALEc);
                    } else if (mode == 1) {
                        int b = r / Nc, nn = r % Nc;
                        int two = cidx >> 8; int c2 = cidx & 255;
                        int h = c2 >> 5, d = c2 & 31;
                        if (two)
                            g_vt[(((size_t)b*HDSc + h)*HDc + d)*NcP + nn] = __float2bfloat16(v);
                        else
                            g_kh[(((size_t)b*HDSc + h)*Nc + nn)*HDc + d] = __float2bfloat16(v);
                    } else if (mode == 2) {
                        v += bias[cidx] + resid[(size_t)r*256 + cidx];
                        g_xres[(size_t)r*256 + cidx] = v;
                    } else if (mode == 3) {
                        v += bias[cidx];
                        v = 0.5f * v * (1.f + erff(v * 0.70710678118654752f));
                        g_hbuf[(size_t)r*1024 + cidx] = v;
                    } else {
                        v += bias[cidx] + resid[(size_t)r*256 + cidx];
                        int b = r / NTc, p = r % NTc;
                        out[((size_t)b*Cdim + cidx)*NTc + p] = v;
                    }
                }
            }
        }
    }
}

// ---------------- SINGLE-PASS attention: 2-moment Taylor -------------------
// w = exp(p), p = e/lB with p <= ~8e-4 for B-segment (lB sums 2304 e's of
// magnitude ~1) -> exp(p) = 1 + p, trunc err p^2/2 ~ 3e-7 (invisible).
// Accumulate T0 = sum mask*v, T1 = sum mask*e*v, den0, den1 and lB in ONE
// pass. A-segment (20 cols, tile 0 only; lA complete after tile 0) handled
// EXACTLY via __expf, folded into T0/den0.
// grid: (NT/128, B*HDS), block 256
__global__ __launch_bounds__(256) void attn_kernel(
    const float* __restrict__ mask, float* __restrict__ out)
{
    __shared__ __nv_bfloat16 Ks[2][64][40];
    __shared__ __nv_bfloat16 Vt[2][32][72];

    int bh = blockIdx.y;
    int b = bh >> 3, h = bh & 7;
    int m0 = blockIdx.x * 128;
    const __nv_bfloat16* Qg = g_qh + ((size_t)bh*NTc + m0)*HDc;
    const __nv_bfloat16* Kg = g_kh + (size_t)bh*Nc*HDc;
    const __nv_bfloat16* Vg = g_vt + (size_t)bh*HDc*NcP;
    const float* Mk = mask + ((size_t)bh*Nc + CLSc + m0)*Nc;

    int t = threadIdx.x;
    int wr = t >> 5, lane = t & 31;
    int qr = lane >> 2, c0 = (lane & 3) * 2;
    int r = wr*16 + qr;
    int krow = t >> 2, kseg = t & 3;        // K loader mapping
    int vd = t >> 3, vseg = t & 7;          // V loader mapping

    unsigned aq[2][4];
#pragma unroll
    for (int kk = 0; kk < 2; kk++) {
        aq[kk][0] = *(const unsigned*)&Qg[(size_t)r    *HDc + kk*16 + c0];
        aq[kk][1] = *(const unsigned*)&Qg[(size_t)(r+8)*HDc + kk*16 + c0];
        aq[kk][2] = *(const unsigned*)&Qg[(size_t)r    *HDc + kk*16 + c0 + 8];
        aq[kk][3] = *(const unsigned*)&Qg[(size_t)(r+8)*HDc + kk*16 + c0 + 8];
    }

    // prologue: load tile 0 K/V directly to smem[0]
    {
        float4 kv = make_float4(0.f,0.f,0.f,0.f);
        if (krow < Nc)
            kv = *(const float4*)&Kg[(size_t)krow*HDc + kseg*8];
        *(float4*)&Ks[0][krow][kseg*8] = kv;
        float4 vv = *(const float4*)&Vg[(size_t)vd*NcP + vseg*8];
        *(float4*)&Vt[0][vd][vseg*8] = vv;
    }

    float lB[2] = {0.f, 0.f};
    float ilA[2] = {0.f, 0.f};
    float den0[2] = {0.f,0.f}, den1[2] = {0.f,0.f};
    float T0[4][4], T1[4][4];
#pragma unroll
    for (int jd = 0; jd < 4; jd++)
#pragma unroll
        for (int e = 0; e < 4; e++) { T0[jd][e]=0.f; T1[jd][e]=0.f; }

    const int NTILES = 37;  // 37*64 = 2368 >= Nc
    float4 kpre, vpre;

    for (int it = 0; it < NTILES; it++) {
        __syncthreads();
        int cur = it & 1, nxt = cur ^ 1;
        int n0 = it * 64;

        // prefetch next K/V tile to regs
        if (it + 1 < NTILES) {
            int nn0 = n0 + 64;
            kpre = make_float4(0.f,0.f,0.f,0.f);
            if (nn0 + krow < Nc)
                kpre = *(const float4*)&Kg[(size_t)(nn0+krow)*HDc + kseg*8];
            vpre = make_float4(0.f,0.f,0.f,0.f);
            if (nn0 + vseg*8 + 8 <= NcP)
                vpre = *(const float4*)&Vg[(size_t)vd*NcP + nn0 + vseg*8];
        }

        // mask tile -> 1 bit per element (32 bits total)
        // Nc even and np even => np<Nc implies np+1<Nc (no partial pair).
        unsigned mbits = 0;
#pragma unroll
        for (int j = 0; j < 8; j++) {
            int np = n0 + j*8 + c0;
            if (np < Nc) {
                float2 m0v = *(const float2*)&Mk[(size_t)r    *Nc + np];
                float2 m1v = *(const float2*)&Mk[(size_t)(r+8)*Nc + np];
                if (m0v.x >= MRc) mbits |= 1u << (j*4+0);
                if (m0v.y >= MRc) mbits |= 1u << (j*4+1);
                if (m1v.x >= MRc) mbits |= 1u << (j*4+2);
                if (m1v.y >= MRc) mbits |= 1u << (j*4+3);
            }
        }

        // S = Q K^T for this tile
        float sacc[8][4];
#pragma unroll
        for (int j = 0; j < 8; j++) { sacc[j][0]=0.f; sacc[j][1]=0.f; sacc[j][2]=0.f; sacc[j][3]=0.f; }
#pragma unroll
        for (int j = 0; j < 8; j++) {
#pragma unroll
            for (int kk = 0; kk < 2; kk++) {
                unsigned bv[2];
                bv[0] = *(const unsigned*)&Ks[cur][j*8 + qr][kk*16 + c0];
                bv[1] = *(const unsigned*)&Ks[cur][j*8 + qr][kk*16 + c0 + 8];
                mma16816(sacc[j], aq[kk], bv);
            }
        }

        // tile 0: finish lA (A-segment complete), get ilA
        if (it == 0) {
            float lAx[2] = {0.f, 0.f};
#pragma unroll
            for (int j = 0; j < 3; j++)
#pragma unroll
                for (int ri = 0; ri < 2; ri++)
#pragma unroll
                    for (int e = 0; e < 2; e++) {
                        int n = j*8 + c0 + e;
                        if (n < CLSc) lAx[ri] += __expf(sacc[j][ri*2+e]);
                    }
#pragma unroll
            for (int ri = 0; ri < 2; ri++) {
                lAx[ri] += __shfl_xor_sync(0xffffffffu, lAx[ri], 1);
                lAx[ri] += __shfl_xor_sync(0xffffffffu, lAx[ri], 2);
                ilA[ri] = 1.f / lAx[ri];
            }
        }

        // moment construction + 2 PV MMA sets
#pragma unroll
        for (int kk = 0; kk < 4; kk++) {
            unsigned ap0[4], ap1[4];
#pragma unroll
            for (int jj = 0; jj < 2; jj++) {
                int j = 2*kk + jj;
                int np = n0 + j*8 + c0;
                float tv0[4], tv1[4];
#pragma unroll
                for (int ri = 0; ri < 2; ri++)
#pragma unroll
                    for (int e = 0; e < 2; e++) {
                        int idx = ri*2 + e;
                        int n = np + e;
                        float ex = __expf(sacc[j][idx]);
                        bool isA = (it == 0) && (n < CLSc);
                        bool valid = n < Nc;
                        if (valid && !isA) lB[ri] += ex;
                        bool mok = valid && ((mbits >> (j*4+idx)) & 1u);
                        float a0, a1;
                        if (isA) {
                            a0 = mok ? __expf(ex * ilA[ri]) : 0.f;
                            a1 = 0.f;
                        } else {
                            a0 = mok ? 1.f : 0.f;
                            a1 = mok ? ex : 0.f;
                        }
                        den0[ri] += a0; den1[ri] += a1;
                        tv0[idx] = a0; tv1[idx] = a1;
                    }
                ap0[jj*2+0] = packbf(tv0[0], tv0[1]); ap0[jj*2+1] = packbf(tv0[2], tv0[3]);
                ap1[jj*2+0] = packbf(tv1[0], tv1[1]); ap1[jj*2+1] = packbf(tv1[2], tv1[3]);
            }
#pragma unroll
            for (int jd = 0; jd < 4; jd++) {
                unsigned bv[2];
                bv[0] = *(const unsigned*)&Vt[cur][jd*8 + qr][kk*16 + c0];
                bv[1] = *(const unsigned*)&Vt[cur][jd*8 + qr][kk*16 + c0 + 8];
                mma16816(T0[jd], ap0, bv);
                mma16816(T1[jd], ap1, bv);
            }
        }

        // store prefetched tile into the other buffer
        if (it + 1 < NTILES) {
            *(float4*)&Ks[nxt][krow][kseg*8] = kpre;
            *(float4*)&Vt[nxt][vd][vseg*8] = vpre;
        }
    }

    // finalize: reduce lB, combine moments
    float ilB[2], inv[2];
#pragma unroll
    for (int ri = 0; ri < 2; ri++) {
        lB[ri] += __shfl_xor_sync(0xffffffffu, lB[ri], 1);
        lB[ri] += __shfl_xor_sync(0xffffffffu, lB[ri], 2);
        ilB[ri] = 1.f / lB[ri];
        float dc = den0[ri] + ilB[ri]*den1[ri];
        dc += __shfl_xor_sync(0xffffffffu, dc, 1);
        dc += __shfl_xor_sync(0xffffffffu, dc, 2);
        inv[ri] = 1.f / dc;
    }

#pragma unroll
    for (int jd = 0; jd < 4; jd++) {
        int col = h*HDc + jd*8 + c0;
        float v0 = (T0[jd][0] + ilB[0]*T1[jd][0]) * inv[0];
        float v1 = (T0[jd][1] + ilB[0]*T1[jd][1]) * inv[0];
        float v2 = (T0[jd][2] + ilB[1]*T1[jd][2]) * inv[1];
        float v3 = (T0[jd][3] + ilB[1]*T1[jd][3]) * inv[1];
        size_t o0 = ((size_t)b*NTc + m0 + r    )*Cdim + col;
        size_t o1 = ((size_t)b*NTc + m0 + r + 8)*Cdim + col;
        *(float2*)&out[o0] = make_float2(v0, v1);
        *(float2*)&out[o1] = make_float2(v2, v3);
    }
}

// ---------------- launch ----------------
extern "C" void kernel_launch(void* const* d_in, const int* in_sizes, int n_in,
                              void* d_out, int out_size)
{
    const float* x_query = (const float*)d_in[0];
    const float* x_key   = (const float*)d_in[1];
    const float* mask_u  = (const float*)d_in[2];
    const float* g1  = (const float*)d_in[3];
    const float* be1 = (const float*)d_in[4];
    const float* g2  = (const float*)d_in[5];
    const float* be2 = (const float*)d_in[6];
    const float* g3  = (const float*)d_in[7];
    const float* be3 = (const float*)d_in[8];
    const float* Wq  = (const float*)d_in[9];
    const float* Wkv = (const float*)d_in[10];
    const float* Wp  = (const float*)d_in[12];
    const float* bp  = (const float*)d_in[13];
    const float* W1  = (const float*)d_in[14];
    const float* bf1 = (const float*)d_in[15];
    const float* W2  = (const float*)d_in[16];
    const float* bf2 = (const float*)d_in[17];
    float* out = (float*)d_out;

    float *xqt, *qin, *kin, *xattn, *xres, *xln, *hbuf;
    cudaGetSymbolAddress((void**)&xqt,   g_xqt);
    cudaGetSymbolAddress((void**)&qin,   g_qin);
    cudaGetSymbolAddress((void**)&kin,   g_kin);
    cudaGetSymbolAddress((void**)&xattn, g_xattn);
    cudaGetSymbolAddress((void**)&xres,  g_xres);
    cudaGetSymbolAddress((void**)&xln,   g_xln);
    cudaGetSymbolAddress((void**)&hbuf,  g_hbuf);

    ln_q_kernel<<<dim3(NTc/32, Bc), 256>>>(x_query, g1, be1, xqt, qin);
    ln_row_kernel<<<Bc*Nc, 256>>>(x_key, g2, be2, kin);
    sgemm_tc<<<dim3((Bc*NTc)/128, Cdim/64), 256>>>(qin, Wq, Bc*NTc, Cdim, KDc, 0, nullptr, nullptr, nullptr);
    sgemm_tc<<<dim3((Bc*Nc+127)/128, (2*Cdim)/64), 256>>>(kin, Wkv, Bc*Nc, 2*Cdim, KDc, 1, nullptr, nullptr, nullptr);
    attn_kernel<<<dim3(NTc/128, Bc*HDSc), 256>>>(mask_u, xattn);
    sgemm_tc<<<dim3((Bc*NTc)/128, Cdim/64), 256>>>(xattn, Wp, Bc*NTc, Cdim, Cdim, 2, bp, xqt, nullptr);
    ln_row_kernel<<<Bc*NTc, 256>>>(xres, g3, be3, xln);
    sgemm_tc<<<dim3((Bc*NTc)/128, (4*Cdim)/64), 256>>>(xln, W1, Bc*NTc, 4*Cdim, Cdim, 3, bf1, nullptr, nullptr);
    sgemm_tc<<<dim3((Bc*NTc)/128, Cdim/64), 256>>>(hbuf, W2, Bc*NTc, Cdim, 4*Cdim, 4, bf2, xres, out);
}

// round 13
// speedup vs baseline: 1.0056x; 1.0056x over previous
#include <cuda_runtime.h>
#include <cuda_bf16.h>
#include <math.h>

#define Bc 2
#define Cdim 256
#define NTc 2304
#define KDc 256
#define CLSc 20
#define Nc 2324
#define NcP 2336
#define HDSc 8
#define HDc 32
#define SCALEc 0.17677669529663687f
#define EPSc 1e-5f
#define MRc 0.3f

// ---------------- device scratch ----------------
__device__ float g_xqt[Bc*NTc*Cdim];
__device__ float g_qin[Bc*NTc*Cdim];
__device__ float g_kin[Bc*Nc*KDc];
__device__ __nv_bfloat16 g_qh[Bc*HDSc*NTc*HDc];   // q*SCALE, (bh, m, d) bf16
__device__ __nv_bfloat16 g_kh[Bc*HDSc*Nc*HDc];    // k (bh, n, d) bf16
__device__ __nv_bfloat16 g_vt[Bc*HDSc*HDc*NcP];   // v transposed (bh, d, n) bf16 (pad cols 0)
__device__ float g_xattn[Bc*NTc*Cdim];
__device__ float g_xres [Bc*NTc*Cdim];
__device__ float g_xln  [Bc*NTc*Cdim];
__device__ float g_hbuf [Bc*NTc*4*Cdim];

__device__ __forceinline__ void mma16816(float* c, const unsigned* a, const unsigned* b){
    asm volatile(
        "mma.sync.aligned.m16n8k16.row.col.f32.bf16.bf16.f32 "
        "{%0,%1,%2,%3}, {%4,%5,%6,%7}, {%8,%9}, {%0,%1,%2,%3};\n"
        : "+f"(c[0]), "+f"(c[1]), "+f"(c[2]), "+f"(c[3])
        : "r"(a[0]), "r"(a[1]), "r"(a[2]), "r"(a[3]), "r"(b[0]), "r"(b[1]));
}
__device__ __forceinline__ void mma1688_tf32(float* c, const unsigned* a, const unsigned* b){
    asm volatile(
        "mma.sync.aligned.m16n8k8.row.col.f32.tf32.tf32.f32 "
        "{%0,%1,%2,%3}, {%4,%5,%6,%7}, {%8,%9}, {%0,%1,%2,%3};\n"
        : "+f"(c[0]), "+f"(c[1]), "+f"(c[2]), "+f"(c[3])
        : "r"(a[0]), "r"(a[1]), "r"(a[2]), "r"(a[3]), "r"(b[0]), "r"(b[1]));
}
__device__ __forceinline__ unsigned f2tf32(float x){
    unsigned r;
    asm("cvt.rna.tf32.f32 %0, %1;" : "=r"(r) : "f"(x));
    return r;
}
__device__ __forceinline__ unsigned packbf(float lo, float hi){
    __nv_bfloat162 t = __floats2bfloat162_rn(lo, hi);
    return *(unsigned*)&t;
}

// ---------------- LN over transposed x_query ----------
__global__ __launch_bounds__(256) void ln_q_kernel(
    const float* __restrict__ xq, const float* __restrict__ g,
    const float* __restrict__ be, float* __restrict__ out_raw,
    float* __restrict__ out_ln)
{
    __shared__ float tile[256][33];
    __shared__ float redS[8][32], redQ[8][32];
    __shared__ float s_mean[32], s_rstd[32];
    int b = blockIdx.y;
    int p0 = blockIdx.x * 32;
    int t = threadIdx.x;
    int pl = t & 31, grp = t >> 5;
    const float* src = xq + (size_t)b*Cdim*NTc + p0 + pl;
#pragma unroll
    for (int cc = 0; cc < 32; cc++) {
        int c = cc*8 + grp;
        tile[c][pl] = src[(size_t)c*NTc];
    }
    __syncthreads();
    float s = 0.f, q = 0.f;
#pragma unroll
    for (int j = 0; j < 32; j++) {
        float v = tile[grp*32 + j][pl];
        s += v; q += v*v;
    }
    redS[grp][pl] = s; redQ[grp][pl] = q;
    __syncthreads();
    if (grp == 0) {
        float S = 0.f, Q = 0.f;
#pragma unroll
        for (int i = 0; i < 8; i++) { S += redS[i][pl]; Q += redQ[i][pl]; }
        float m = S * (1.f/256.f);
        float var = Q * (1.f/256.f) - m*m;
        s_mean[pl] = m;
        s_rstd[pl] = rsqrtf(var + EPSc);
    }
    __syncthreads();
    float gg = g[t], bb = be[t];
    for (int p = 0; p < 32; p++) {
        float v = tile[t][p];
        size_t o = ((size_t)b*NTc + p0 + p)*Cdim + t;
        out_raw[o] = v;
        out_ln[o]  = (v - s_mean[p]) * s_rstd[p] * gg + bb;
    }
}

// ---------------- row LN ----------------
__global__ __launch_bounds__(256) void ln_row_kernel(
    const float* __restrict__ x, const float* __restrict__ g,
    const float* __restrict__ be, float* __restrict__ y)
{
    int r = blockIdx.x;
    int t = threadIdx.x;
    float v = x[(size_t)r*256 + t];
    float s = v, q = v*v;
#pragma unroll
    for (int off = 16; off >= 1; off >>= 1) {
        s += __shfl_xor_sync(0xffffffffu, s, off);
        q += __shfl_xor_sync(0xffffffffu, q, off);
    }
    __shared__ float ss[8], sq[8];
    __shared__ float s_mean, s_rstd;
    int warp = t >> 5, lane = t & 31;
    if (lane == 0) { ss[warp] = s; sq[warp] = q; }
    __syncthreads();
    if (t == 0) {
        float S = 0.f, Q = 0.f;
#pragma unroll
        for (int i = 0; i < 8; i++) { S += ss[i]; Q += sq[i]; }
        float m = S * (1.f/256.f);
        float var = Q * (1.f/256.f) - m*m;
        s_mean = m;
        s_rstd = rsqrtf(var + EPSc);
    }
    __syncthreads();
    y[(size_t)r*256 + t] = (v - s_mean) * s_rstd * g[t] + be[t];
}

// ---------------- TF32 GEMM, BM=128 BN=64 BK=32, 2-stage pipeline ----------
__global__ __launch_bounds__(256) void sgemm_tc(
    const float* __restrict__ A, const float* __restrict__ Bw,
    int Mrows, int Ncols, int Kdim, int mode,
    const float* __restrict__ bias, const float* __restrict__ resid,
    float* __restrict__ out)
{
    __shared__ unsigned As[2][128][36];
    __shared__ unsigned Bs[2][32][68];

    int m0 = blockIdx.x * 128, n0 = blockIdx.y * 64;
    int t = threadIdx.x;
    int wid = t >> 5, lane = t & 31;
    int wm = wid & 3, wn = wid >> 2;
    int qr = lane >> 2, tig = lane & 3;

    float c[2][4][4];
#pragma unroll
    for (int mt = 0; mt < 2; mt++)
#pragma unroll
        for (int nt = 0; nt < 4; nt++)
#pragma unroll
            for (int e = 0; e < 4; e++) c[mt][nt][e] = 0.f;

    int ar = t >> 3, ac4 = (t & 7) * 4;
    int br = t >> 4, bc4 = (t & 15) * 4;
    int nit = Kdim >> 5;

    float4 aReg[4], bReg[2];
#pragma unroll
    for (int i = 0; i < 4; i++) {
        int row = ar + i*32;
        aReg[i] = make_float4(0.f,0.f,0.f,0.f);
        if (m0 + row < Mrows)
            aReg[i] = *(const float4*)&A[(size_t)(m0+row)*Kdim + ac4];
    }
#pragma unroll
    for (int i = 0; i < 2; i++)
        bReg[i] = *(const float4*)&Bw[(size_t)(br + i*16)*Ncols + n0 + bc4];
#pragma unroll
    for (int i = 0; i < 4; i++) {
        int row = ar + i*32;
        As[0][row][ac4+0] = f2tf32(aReg[i].x); As[0][row][ac4+1] = f2tf32(aReg[i].y);
        As[0][row][ac4+2] = f2tf32(aReg[i].z); As[0][row][ac4+3] = f2tf32(aReg[i].w);
    }
#pragma unroll
    for (int i = 0; i < 2; i++) {
        int row = br + i*16;
        Bs[0][row][bc4+0] = f2tf32(bReg[i].x); Bs[0][row][bc4+1] = f2tf32(bReg[i].y);
        Bs[0][row][bc4+2] = f2tf32(bReg[i].z); Bs[0][row][bc4+3] = f2tf32(bReg[i].w);
    }

    for (int it = 0; it < nit; it++) {
        __syncthreads();
        int cur = it & 1, nxt = cur ^ 1;
        if (it + 1 < nit) {
            int k0 = (it + 1) << 5;
#pragma unroll
            for (int i = 0; i < 4; i++) {
                int row = ar + i*32;
                aReg[i] = make_float4(0.f,0.f,0.f,0.f);
                if (m0 + row < Mrows)
                    aReg[i] = *(const float4*)&A[(size_t)(m0+row)*Kdim + k0 + ac4];
            }
#pragma unroll
            for (int i = 0; i < 2; i++)
                bReg[i] = *(const float4*)&Bw[(size_t)(k0 + br + i*16)*Ncols + n0 + bc4];
        }

#pragma unroll
        for (int kk = 0; kk < 32; kk += 8) {
            unsigned afr[2][4], bfr[4][2];
#pragma unroll
            for (int mt = 0; mt < 2; mt++) {
                int rb = wm*32 + mt*16;
                afr[mt][0] = As[cur][rb + qr    ][kk + tig];
                afr[mt][1] = As[cur][rb + qr + 8][kk + tig];
                afr[mt][2] = As[cur][rb + qr    ][kk + tig + 4];
                afr[mt][3] = As[cur][rb + qr + 8][kk + tig + 4];
            }
#pragma unroll
            for (int nt = 0; nt < 4; nt++) {
                int cb = wn*32 + nt*8 + qr;
                bfr[nt][0] = Bs[cur][kk + tig    ][cb];
                bfr[nt][1] = Bs[cur][kk + tig + 4][cb];
            }
#pragma unroll
            for (int mt = 0; mt < 2; mt++)
#pragma unroll
                for (int nt = 0; nt < 4; nt++)
                    mma1688_tf32(c[mt][nt], afr[mt], bfr[nt]);
        }

        if (it + 1 < nit) {
#pragma unroll
            for (int i = 0; i < 4; i++) {
                int row = ar + i*32;
                As[nxt][row][ac4+0] = f2tf32(aReg[i].x); As[nxt][row][ac4+1] = f2tf32(aReg[i].y);
                As[nxt][row][ac4+2] = f2tf32(aReg[i].z); As[nxt][row][ac4+3] = f2tf32(aReg[i].w);
            }
#pragma unroll
            for (int i = 0; i < 2; i++) {
                int row = br + i*16;
                Bs[nxt][row][bc4+0] = f2tf32(bReg[i].x); Bs[nxt][row][bc4+1] = f2tf32(bReg[i].y);
                Bs[nxt][row][bc4+2] = f2tf32(bReg[i].z); Bs[nxt][row][bc4+3] = f2tf32(bReg[i].w);
            }
        }
    }

#pragma unroll
    for (int mt = 0; mt < 2; mt++) {
#pragma unroll
        for (int ri = 0; ri < 2; ri++) {
            int r = m0 + wm*32 + mt*16 + qr + ri*8;
            if (r >= Mrows) continue;
#pragma unroll
            for (int nt = 0; nt < 4; nt++) {
#pragma unroll
                for (int e = 0; e < 2; e++) {
                    int cidx = n0 + wn*32 + nt*8 + tig*2 + e;
                    float v = c[mt][nt][ri*2 + e];
                    if (mode == 0) {
                        int b = r / NTc, ii = r % NTc;
                        int h = cidx >> 5, d = cidx & 31;
                        g_qh[(((size_t)b*HDSc + h)*NTc + ii)*HDc + d] = __float2bfloat16(v * SCALEc);
                    } else if (mode == 1) {
                        int b = r / Nc, nn = r % Nc;
                        int two = cidx >> 8; int c2 = cidx & 255;
                        int h = c2 >> 5, d = c2 & 31;
                        if (two)
                            g_vt[(((size_t)b*HDSc + h)*HDc + d)*NcP + nn] = __float2bfloat16(v);
                        else
                            g_kh[(((size_t)b*HDSc + h)*Nc + nn)*HDc + d] = __float2bfloat16(v);
                    } else if (mode == 2) {
                        v += bias[cidx] + resid[(size_t)r*256 + cidx];
                        g_xres[(size_t)r*256 + cidx] = v;
                    } else if (mode == 3) {
                        v += bias[cidx];
                        v = 0.5f * v * (1.f + erff(v * 0.70710678118654752f));
                        g_hbuf[(size_t)r*1024 + cidx] = v;
                    } else {
                        v += bias[cidx] + resid[(size_t)r*256 + cidx];
                        int b = r / NTc, p = r % NTc;
                        out[((size_t)b*Cdim + cidx)*NTc + p] = v;
                    }
                }
            }
        }
    }
}

// ---------------- two-pass masked attention, double-buffered tiles ---------
// no-max softmax (scores bounded); pass-2 exp(p) via Taylor for B segment.
// grid: (NT/128, B*HDS), block 256
__global__ __launch_bounds__(256) void attn_kernel(
    const float* __restrict__ mask, float* __restrict__ out)
{
    __shared__ __nv_bfloat16 Ks[2][64][40];
    __shared__ __nv_bfloat16 Vt[2][32][72];

    int bh = blockIdx.y;
    int b = bh >> 3, h = bh & 7;
    int m0 = blockIdx.x * 128;
    const __nv_bfloat16* Qg = g_qh + ((size_t)bh*NTc + m0)*HDc;
    const __nv_bfloat16* Kg = g_kh + (size_t)bh*Nc*HDc;
    const __nv_bfloat16* Vg = g_vt + (size_t)bh*HDc*NcP;
    const float* Mk = mask + ((size_t)bh*Nc + CLSc + m0)*Nc;

    int t = threadIdx.x;
    int wr = t >> 5, lane = t & 31;
    int qr = lane >> 2, c0 = (lane & 3) * 2;
    int r = wr*16 + qr;
    int krow = t >> 2, kseg = t & 3;
    int vd = t >> 3, vseg = t & 7;

    unsigned aq[2][4];
#pragma unroll
    for (int kk = 0; kk < 2; kk++) {
        aq[kk][0] = *(const unsigned*)&Qg[(size_t)r    *HDc + kk*16 + c0];
        aq[kk][1] = *(const unsigned*)&Qg[(size_t)(r+8)*HDc + kk*16 + c0];
        aq[kk][2] = *(const unsigned*)&Qg[(size_t)r    *HDc + kk*16 + c0 + 8];
        aq[kk][3] = *(const unsigned*)&Qg[(size_t)(r+8)*HDc + kk*16 + c0 + 8];
    }

    const int NTILES = 37;  // 37*64 = 2368 >= Nc
    float lA[2] = {0.f, 0.f}, lB[2] = {0.f, 0.f};
    float4 kpre, vpre;

    // ---------------- pass 1: segment sumexp (K only, double-buffered) -----
    {
        float4 kv = make_float4(0.f,0.f,0.f,0.f);
        if (krow < Nc)
            kv = *(const float4*)&Kg[(size_t)krow*HDc + kseg*8];
        *(float4*)&Ks[0][krow][kseg*8] = kv;
    }
    for (int it = 0; it < NTILES; it++) {
        __syncthreads();
        int cur = it & 1, nxt = cur ^ 1;
        int n0 = it * 64;

        if (it + 1 < NTILES) {
            int nn0 = n0 + 64;
            kpre = make_float4(0.f,0.f,0.f,0.f);
            if (nn0 + krow < Nc)
                kpre = *(const float4*)&Kg[(size_t)(nn0+krow)*HDc + kseg*8];
        }

        float sacc[8][4];
#pragma unroll
        for (int j = 0; j < 8; j++) { sacc[j][0]=0.f; sacc[j][1]=0.f; sacc[j][2]=0.f; sacc[j][3]=0.f; }
#pragma unroll
        for (int j = 0; j < 8; j++) {
#pragma unroll
            for (int kk = 0; kk < 2; kk++) {
                unsigned bv[2];
                bv[0] = *(const unsigned*)&Ks[cur][j*8 + qr][kk*16 + c0];
                bv[1] = *(const unsigned*)&Ks[cur][j*8 + qr][kk*16 + c0 + 8];
                mma16816(sacc[j], aq[kk], bv);
            }
        }

        if (it == 0) {
#pragma unroll
            for (int j = 0; j < 8; j++)
#pragma unroll
                for (int ri = 0; ri < 2; ri++)
#pragma unroll
                    for (int e = 0; e < 2; e++) {
                        int n = j*8 + c0 + e;
                        float ex = __expf(sacc[j][ri*2+e]);
                        if (n < CLSc) lA[ri] += ex; else lB[ri] += ex;
                    }
        } else {
#pragma unroll
            for (int j = 0; j < 8; j++)
#pragma unroll
                for (int ri = 0; ri < 2; ri++)
#pragma unroll
                    for (int e = 0; e < 2; e++) {
                        int n = n0 + j*8 + c0 + e;
                        if (n < Nc) lB[ri] += __expf(sacc[j][ri*2+e]);
                    }
        }

        if (it + 1 < NTILES)
            *(float4*)&Ks[nxt][krow][kseg*8] = kpre;
    }

#pragma unroll
    for (int ri = 0; ri < 2; ri++) {
        lA[ri] += __shfl_xor_sync(0xffffffffu, lA[ri], 1);
        lA[ri] += __shfl_xor_sync(0xffffffffu, lA[ri], 2);
        lB[ri] += __shfl_xor_sync(0xffffffffu, lB[ri], 1);
        lB[ri] += __shfl_xor_sync(0xffffffffu, lB[ri], 2);
    }
    float ilA[2], ilB[2], den[2] = {0.f, 0.f};
#pragma unroll
    for (int ri = 0; ri < 2; ri++) { ilA[ri] = 1.f/lA[ri]; ilB[ri] = 1.f/lB[ri]; }

    float oacc[4][4];
#pragma unroll
    for (int jd = 0; jd < 4; jd++) { oacc[jd][0]=0.f; oacc[jd][1]=0.f; oacc[jd][2]=0.f; oacc[jd][3]=0.f; }

    // ---------------- pass 2 (K+V, double-buffered) ----------------
    __syncthreads();  // pass-1 readers of Ks[0] done before reload
    {
        float4 kv = make_float4(0.f,0.f,0.f,0.f);
        if (krow < Nc)
            kv = *(const float4*)&Kg[(size_t)krow*HDc + kseg*8];
        *(float4*)&Ks[0][krow][kseg*8] = kv;
        float4 vv = *(const float4*)&Vg[(size_t)vd*NcP + vseg*8];
        *(float4*)&Vt[0][vd][vseg*8] = vv;
    }
    for (int it = 0; it < NTILES; it++) {
        __syncthreads();
        int cur = it & 1, nxt = cur ^ 1;
        int n0 = it * 64;

        if (it + 1 < NTILES) {
            int nn0 = n0 + 64;
            kpre = make_float4(0.f,0.f,0.f,0.f);
            if (nn0 + krow < Nc)
                kpre = *(const float4*)&Kg[(size_t)(nn0+krow)*HDc + kseg*8];
            vpre = make_float4(0.f,0.f,0.f,0.f);
            if (nn0 + vseg*8 + 8 <= NcP)
                vpre = *(const float4*)&Vg[(size_t)vd*NcP + nn0 + vseg*8];
        }

        // mask tile -> 1 bit per element (Nc even, np even => pair never splits)
        unsigned mbits = 0;
#pragma unroll
        for (int j = 0; j < 8; j++) {
            int np = n0 + j*8 + c0;
            if (np < Nc) {
                float2 m0v = *(const float2*)&Mk[(size_t)r    *Nc + np];
                float2 m1v = *(const float2*)&Mk[(size_t)(r+8)*Nc + np];
                if (m0v.x >= MRc) mbits |= 1u << (j*4+0);
                if (m0v.y >= MRc) mbits |= 1u << (j*4+1);
                if (m1v.x >= MRc) mbits |= 1u << (j*4+2);
                if (m1v.y >= MRc) mbits |= 1u << (j*4+3);
            }
        }

        float sacc[8][4];
#pragma unroll
        for (int j = 0; j < 8; j++) { sacc[j][0]=0.f; sacc[j][1]=0.f; sacc[j][2]=0.f; sacc[j][3]=0.f; }
#pragma unroll
        for (int j = 0; j < 8; j++) {
#pragma unroll
            for (int kk = 0; kk < 2; kk++) {
                unsigned bv[2];
                bv[0] = *(const unsigned*)&Ks[cur][j*8 + qr][kk*16 + c0];
                bv[1] = *(const unsigned*)&Ks[cur][j*8 + qr][kk*16 + c0 + 8];
                mma16816(sacc[j], aq[kk], bv);
            }
        }

#pragma unroll
        for (int j = 0; j < 8; j++) {
            int np = n0 + j*8 + c0;
#pragma unroll
            for (int ri = 0; ri < 2; ri++)
#pragma unroll
                for (int e = 0; e < 2; e++) {
                    int idx = ri*2 + e;
                    int n = np + e;
                    float w = 0.f;
                    if (n < Nc && ((mbits >> (j*4+idx)) & 1u)) {
                        float ex = __expf(sacc[j][idx]);
                        if (n < CLSc) {
                            w = __expf(ex * ilA[ri]);
                        } else {
                            float p = ex * ilB[ri];
                            w = 1.f + p*(1.f + p*(0.5f + p*(0.16666667f + p*0.04166667f)));
                        }
                    }
                    den[ri] += w;
                    sacc[j][idx] = w;
                }
        }

#pragma unroll
        for (int kk = 0; kk < 4; kk++) {
            unsigned ap[4];
            ap[0] = packbf(sacc[2*kk  ][0], sacc[2*kk  ][1]);
            ap[1] = packbf(sacc[2*kk  ][2], sacc[2*kk  ][3]);
            ap[2] = packbf(sacc[2*kk+1][0], sacc[2*kk+1][1]);
            ap[3] = packbf(sacc[2*kk+1][2], sacc[2*kk+1][3]);
#pragma unroll
            for (int jd = 0; jd < 4; jd++) {
                unsigned bv[2];
                bv[0] = *(const unsigned*)&Vt[cur][jd*8 + qr][kk*16 + c0];
                bv[1] = *(const unsigned*)&Vt[cur][jd*8 + qr][kk*16 + c0 + 8];
                mma16816(oacc[jd], ap, bv);
            }
        }

        if (it + 1 < NTILES) {
            *(float4*)&Ks[nxt][krow][kseg*8] = kpre;
            *(float4*)&Vt[nxt][vd][vseg*8] = vpre;
        }
    }

#pragma unroll
    for (int ri = 0; ri < 2; ri++) {
        den[ri] += __shfl_xor_sync(0xffffffffu, den[ri], 1);
        den[ri] += __shfl_xor_sync(0xffffffffu, den[ri], 2);
    }
    float inv0 = 1.f/den[0], inv1 = 1.f/den[1];
#pragma unroll
    for (int jd = 0; jd < 4; jd++) {
        int col = h*HDc + jd*8 + c0;
        size_t o0 = ((size_t)b*NTc + m0 + r    )*Cdim + col;
        size_t o1 = ((size_t)b*NTc + m0 + r + 8)*Cdim + col;
        *(float2*)&out[o0] = make_float2(oacc[jd][0]*inv0, oacc[jd][1]*inv0);
        *(float2*)&out[o1] = make_float2(oacc[jd][2]*inv1, oacc[jd][3]*inv1);
    }
}

// ---------------- launch ----------------
extern "C" void kernel_launch(void* const* d_in, const int* in_sizes, int n_in,
                              void* d_out, int out_size)
{
    const float* x_query = (const float*)d_in[0];
    const float* x_key   = (const float*)d_in[1];
    const float* mask_u  = (const float*)d_in[2];
    const float* g1  = (const float*)d_in[3];
    const float* be1 = (const float*)d_in[4];
    const float* g2  = (const float*)d_in[5];
    const float* be2 = (const float*)d_in[6];
    const float* g3  = (const float*)d_in[7];
    const float* be3 = (const float*)d_in[8];
    const float* Wq  = (const float*)d_in[9];
    const float* Wkv = (const float*)d_in[10];
    const float* Wp  = (const float*)d_in[12];
    const float* bp  = (const float*)d_in[13];
    const float* W1  = (const float*)d_in[14];
    const float* bf1 = (const float*)d_in[15];
    const float* W2  = (const float*)d_in[16];
    const float* bf2 = (const float*)d_in[17];
    float* out = (float*)d_out;

    float *xqt, *qin, *kin, *xattn, *xres, *xln, *hbuf;
    cudaGetSymbolAddress((void**)&xqt,   g_xqt);
    cudaGetSymbolAddress((void**)&qin,   g_qin);
    cudaGetSymbolAddress((void**)&kin,   g_kin);
    cudaGetSymbolAddress((void**)&xattn, g_xattn);
    cudaGetSymbolAddress((void**)&xres,  g_xres);
    cudaGetSymbolAddress((void**)&xln,   g_xln);
    cudaGetSymbolAddress((void**)&hbuf,  g_hbuf);

    ln_q_kernel<<<dim3(NTc/32, Bc), 256>>>(x_query, g1, be1, xqt, qin);
    ln_row_kernel<<<Bc*Nc, 256>>>(x_key, g2, be2, kin);
    sgemm_tc<<<dim3((Bc*NTc)/128, Cdim/64), 256>>>(qin, Wq, Bc*NTc, Cdim, KDc, 0, nullptr, nullptr, nullptr);
    sgemm_tc<<<dim3((Bc*Nc+127)/128, (2*Cdim)/64), 256>>>(kin, Wkv, Bc*Nc, 2*Cdim, KDc, 1, nullptr, nullptr, nullptr);
    attn_kernel<<<dim3(NTc/128, Bc*HDSc), 256>>>(mask_u, xattn);
    sgemm_tc<<<dim3((Bc*NTc)/128, Cdim/64), 256>>>(xattn, Wp, Bc*NTc, Cdim, Cdim, 2, bp, xqt, nullptr);
    ln_row_kernel<<<Bc*NTc, 256>>>(xres, g3, be3, xln);
    sgemm_tc<<<dim3((Bc*NTc)/128, (4*Cdim)/64), 256>>>(xln, W1, Bc*NTc, 4*Cdim, Cdim, 3, bf1, nullptr, nullptr);
    sgemm_tc<<<dim3((Bc*NTc)/128, Cdim/64), 256>>>(hbuf, W2, Bc*NTc, Cdim, 4*Cdim, 4, bf2, xres, out);
}

// round 14
// speedup vs baseline: 1.1174x; 1.1112x over previous
#include <cuda_runtime.h>
#include <cuda_bf16.h>
#include <math.h>

#define Bc 2
#define Cdim 256
#define NTc 2304
#define KDc 256
#define CLSc 20
#define Nc 2324
#define NcP 2336
#define HDSc 8
#define HDc 32
#define SCALEc 0.17677669529663687f
#define EPSc 1e-5f
#define MRc 0.3f

// ---------------- device scratch ----------------
__device__ float g_xqt[Bc*NTc*Cdim];
__device__ float g_qin[Bc*NTc*Cdim];
__device__ float g_kin[Bc*Nc*KDc];
__device__ __nv_bfloat16 g_qh[Bc*HDSc*NTc*HDc];
__device__ __nv_bfloat16 g_kh[Bc*HDSc*Nc*HDc];
__device__ __nv_bfloat16 g_vt[Bc*HDSc*HDc*NcP];
__device__ float g_xattn[Bc*NTc*Cdim];
__device__ float g_xres [Bc*NTc*Cdim];
__device__ float g_xln  [Bc*NTc*Cdim];
__device__ float g_hbuf [Bc*NTc*4*Cdim];

__device__ __forceinline__ void mma16816(float* c, const unsigned* a, const unsigned* b){
    asm volatile(
        "mma.sync.aligned.m16n8k16.row.col.f32.bf16.bf16.f32 "
        "{%0,%1,%2,%3}, {%4,%5,%6,%7}, {%8,%9}, {%0,%1,%2,%3};\n"
        : "+f"(c[0]), "+f"(c[1]), "+f"(c[2]), "+f"(c[3])
        : "r"(a[0]), "r"(a[1]), "r"(a[2]), "r"(a[3]), "r"(b[0]), "r"(b[1]));
}
__device__ __forceinline__ void mma1688_tf32(float* c, const unsigned* a, const unsigned* b){
    asm volatile(
        "mma.sync.aligned.m16n8k8.row.col.f32.tf32.tf32.f32 "
        "{%0,%1,%2,%3}, {%4,%5,%6,%7}, {%8,%9}, {%0,%1,%2,%3};\n"
        : "+f"(c[0]), "+f"(c[1]), "+f"(c[2]), "+f"(c[3])
        : "r"(a[0]), "r"(a[1]), "r"(a[2]), "r"(a[3]), "r"(b[0]), "r"(b[1]));
}
__device__ __forceinline__ unsigned f2tf32(float x){
    unsigned r;
    asm("cvt.rna.tf32.f32 %0, %1;" : "=r"(r) : "f"(x));
    return r;
}
__device__ __forceinline__ unsigned packbf(float lo, float hi){
    __nv_bfloat162 t = __floats2bfloat162_rn(lo, hi);
    return *(unsigned*)&t;
}

// ---------------- fused LN: x_key rows + x_query transpose-LN --------------
// blockIdx.x < Bc*Nc          : row LN of x_key -> g_kin
// blockIdx.x >= Bc*Nc         : 32-pixel tile of x_query -> g_xqt, g_qin
__global__ __launch_bounds__(256) void ln_fused_kernel(
    const float* __restrict__ xq, const float* __restrict__ g1,
    const float* __restrict__ be1, float* __restrict__ out_raw,
    float* __restrict__ out_ln,
    const float* __restrict__ xk, const float* __restrict__ g2,
    const float* __restrict__ be2, float* __restrict__ kin)
{
    __shared__ float tile[256][33];
    __shared__ float redS[8][32], redQ[8][32];
    __shared__ float s_mean[32], s_rstd[32];
    int t = threadIdx.x;
    if (blockIdx.x < Bc*Nc) {
        // ---- row LN over x_key ----
        int r = blockIdx.x;
        float v = xk[(size_t)r*256 + t];
        float s = v, q = v*v;
#pragma unroll
        for (int off = 16; off >= 1; off >>= 1) {
            s += __shfl_xor_sync(0xffffffffu, s, off);
            q += __shfl_xor_sync(0xffffffffu, q, off);
        }
        int warp = t >> 5, lane = t & 31;
        if (lane == 0) { redS[0][warp] = s; redQ[0][warp] = q; }
        __syncthreads();
        if (t == 0) {
            float S = 0.f, Q = 0.f;
#pragma unroll
            for (int i = 0; i < 8; i++) { S += redS[0][i]; Q += redQ[0][i]; }
            float m = S * (1.f/256.f);
            float var = Q * (1.f/256.f) - m*m;
            s_mean[0] = m;
            s_rstd[0] = rsqrtf(var + EPSc);
        }
        __syncthreads();
        kin[(size_t)r*256 + t] = (v - s_mean[0]) * s_rstd[0] * g2[t] + be2[t];
    } else {
        // ---- transpose-LN over x_query ----
        int bi = blockIdx.x - Bc*Nc;
        int b = bi / (NTc/32);
        int p0 = (bi % (NTc/32)) * 32;
        int pl = t & 31, grp = t >> 5;
        const float* src = xq + (size_t)b*Cdim*NTc + p0 + pl;
#pragma unroll
        for (int cc = 0; cc < 32; cc++) {
            int c = cc*8 + grp;
            tile[c][pl] = src[(size_t)c*NTc];
        }
        __syncthreads();
        float s = 0.f, q = 0.f;
#pragma unroll
        for (int j = 0; j < 32; j++) {
            float v = tile[grp*32 + j][pl];
            s += v; q += v*v;
        }
        redS[grp][pl] = s; redQ[grp][pl] = q;
        __syncthreads();
        if (grp == 0) {
            float S = 0.f, Q = 0.f;
#pragma unroll
            for (int i = 0; i < 8; i++) { S += redS[i][pl]; Q += redQ[i][pl]; }
            float m = S * (1.f/256.f);
            float var = Q * (1.f/256.f) - m*m;
            s_mean[pl] = m;
            s_rstd[pl] = rsqrtf(var + EPSc);
        }
        __syncthreads();
        float gg = g1[t], bb = be1[t];
        for (int p = 0; p < 32; p++) {
            float v = tile[t][p];
            size_t o = ((size_t)b*NTc + p0 + p)*Cdim + t;
            out_raw[o] = v;
            out_ln[o]  = (v - s_mean[p]) * s_rstd[p] * gg + bb;
        }
    }
}

// ---------------- row LN (standalone, for xres) ----------------
__global__ __launch_bounds__(256) void ln_row_kernel(
    const float* __restrict__ x, const float* __restrict__ g,
    const float* __restrict__ be, float* __restrict__ y)
{
    int r = blockIdx.x;
    int t = threadIdx.x;
    float v = x[(size_t)r*256 + t];
    float s = v, q = v*v;
#pragma unroll
    for (int off = 16; off >= 1; off >>= 1) {
        s += __shfl_xor_sync(0xffffffffu, s, off);
        q += __shfl_xor_sync(0xffffffffu, q, off);
    }
    __shared__ float ss[8], sq[8];
    __shared__ float s_mean, s_rstd;
    int warp = t >> 5, lane = t & 31;
    if (lane == 0) { ss[warp] = s; sq[warp] = q; }
    __syncthreads();
    if (t == 0) {
        float S = 0.f, Q = 0.f;
#pragma unroll
        for (int i = 0; i < 8; i++) { S += ss[i]; Q += sq[i]; }
        float m = S * (1.f/256.f);
        float var = Q * (1.f/256.f) - m*m;
        s_mean = m;
        s_rstd = rsqrtf(var + EPSc);
    }
    __syncthreads();
    y[(size_t)r*256 + t] = (v - s_mean) * s_rstd * g[t] + be[t];
}

// ---------------- TF32 GEMM body, BM=128 BN=64 BK=32, 2-stage --------------
__device__ __forceinline__ void sgemm_body(
    const float* __restrict__ A, const float* __restrict__ Bw,
    int Mrows, int Ncols, int Kdim, int mode,
    const float* __restrict__ bias, const float* __restrict__ resid,
    float* __restrict__ out, int mblk, int nblk)
{
    __shared__ unsigned As[2][128][36];
    __shared__ unsigned Bs[2][32][68];

    int m0 = mblk * 128, n0 = nblk * 64;
    int t = threadIdx.x;
    int wid = t >> 5, lane = t & 31;
    int wm = wid & 3, wn = wid >> 2;
    int qr = lane >> 2, tig = lane & 3;

    float c[2][4][4];
#pragma unroll
    for (int mt = 0; mt < 2; mt++)
#pragma unroll
        for (int nt = 0; nt < 4; nt++)
#pragma unroll
            for (int e = 0; e < 4; e++) c[mt][nt][e] = 0.f;

    int ar = t >> 3, ac4 = (t & 7) * 4;
    int br = t >> 4, bc4 = (t & 15) * 4;
    int nit = Kdim >> 5;

    float4 aReg[4], bReg[2];
#pragma unroll
    for (int i = 0; i < 4; i++) {
        int row = ar + i*32;
        aReg[i] = make_float4(0.f,0.f,0.f,0.f);
        if (m0 + row < Mrows)
            aReg[i] = *(const float4*)&A[(size_t)(m0+row)*Kdim + ac4];
    }
#pragma unroll
    for (int i = 0; i < 2; i++)
        bReg[i] = *(const float4*)&Bw[(size_t)(br + i*16)*Ncols + n0 + bc4];
#pragma unroll
    for (int i = 0; i < 4; i++) {
        int row = ar + i*32;
        As[0][row][ac4+0] = f2tf32(aReg[i].x); As[0][row][ac4+1] = f2tf32(aReg[i].y);
        As[0][row][ac4+2] = f2tf32(aReg[i].z); As[0][row][ac4+3] = f2tf32(aReg[i].w);
    }
#pragma unroll
    for (int i = 0; i < 2; i++) {
        int row = br + i*16;
        Bs[0][row][bc4+0] = f2tf32(bReg[i].x); Bs[0][row][bc4+1] = f2tf32(bReg[i].y);
        Bs[0][row][bc4+2] = f2tf32(bReg[i].z); Bs[0][row][bc4+3] = f2tf32(bReg[i].w);
    }

    for (int it = 0; it < nit; it++) {
        __syncthreads();
        int cur = it & 1, nxt = cur ^ 1;
        if (it + 1 < nit) {
            int k0 = (it + 1) << 5;
#pragma unroll
            for (int i = 0; i < 4; i++) {
                int row = ar + i*32;
                aReg[i] = make_float4(0.f,0.f,0.f,0.f);
                if (m0 + row < Mrows)
                    aReg[i] = *(const float4*)&A[(size_t)(m0+row)*Kdim + k0 + ac4];
            }
#pragma unroll
            for (int i = 0; i < 2; i++)
                bReg[i] = *(const float4*)&Bw[(size_t)(k0 + br + i*16)*Ncols + n0 + bc4];
        }

#pragma unroll
        for (int kk = 0; kk < 32; kk += 8) {
            unsigned afr[2][4], bfr[4][2];
#pragma unroll
            for (int mt = 0; mt < 2; mt++) {
                int rb = wm*32 + mt*16;
                afr[mt][0] = As[cur][rb + qr    ][kk + tig];
                afr[mt][1] = As[cur][rb + qr + 8][kk + tig];
                afr[mt][2] = As[cur][rb + qr    ][kk + tig + 4];
                afr[mt][3] = As[cur][rb + qr + 8][kk + tig + 4];
            }
#pragma unroll
            for (int nt = 0; nt < 4; nt++) {
                int cb = wn*32 + nt*8 + qr;
                bfr[nt][0] = Bs[cur][kk + tig    ][cb];
                bfr[nt][1] = Bs[cur][kk + tig + 4][cb];
            }
#pragma unroll
            for (int mt = 0; mt < 2; mt++)
#pragma unroll
                for (int nt = 0; nt < 4; nt++)
                    mma1688_tf32(c[mt][nt], afr[mt], bfr[nt]);
        }

        if (it + 1 < nit) {
#pragma unroll
            for (int i = 0; i < 4; i++) {
                int row = ar + i*32;
                As[nxt][row][ac4+0] = f2tf32(aReg[i].x); As[nxt][row][ac4+1] = f2tf32(aReg[i].y);
                As[nxt][row][ac4+2] = f2tf32(aReg[i].z); As[nxt][row][ac4+3] = f2tf32(aReg[i].w);
            }
#pragma unroll
            for (int i = 0; i < 2; i++) {
                int row = br + i*16;
                Bs[nxt][row][bc4+0] = f2tf32(bReg[i].x); Bs[nxt][row][bc4+1] = f2tf32(bReg[i].y);
                Bs[nxt][row][bc4+2] = f2tf32(bReg[i].z); Bs[nxt][row][bc4+3] = f2tf32(bReg[i].w);
            }
        }
    }

#pragma unroll
    for (int mt = 0; mt < 2; mt++) {
#pragma unroll
        for (int ri = 0; ri < 2; ri++) {
            int r = m0 + wm*32 + mt*16 + qr + ri*8;
            if (r >= Mrows) continue;
#pragma unroll
            for (int nt = 0; nt < 4; nt++) {
#pragma unroll
                for (int e = 0; e < 2; e++) {
                    int cidx = n0 + wn*32 + nt*8 + tig*2 + e;
                    float v = c[mt][nt][ri*2 + e];
                    if (mode == 0) {
                        int b = r / NTc, ii = r % NTc;
                        int h = cidx >> 5, d = cidx & 31;
                        g_qh[(((size_t)b*HDSc + h)*NTc + ii)*HDc + d] = __float2bfloat16(v * SCALEc);
                    } else if (mode == 1) {
                        int b = r / Nc, nn = r % Nc;
                        int two = cidx >> 8; int c2 = cidx & 255;
                        int h = c2 >> 5, d = c2 & 31;
                        if (two)
                            g_vt[(((size_t)b*HDSc + h)*HDc + d)*NcP + nn] = __float2bfloat16(v);
                        else
                            g_kh[(((size_t)b*HDSc + h)*Nc + nn)*HDc + d] = __float2bfloat16(v);
                    } else if (mode == 2) {
                        v += bias[cidx] + resid[(size_t)r*256 + cidx];
                        g_xres[(size_t)r*256 + cidx] = v;
                    } else if (mode == 3) {
                        v += bias[cidx];
                        v = 0.5f * v * (1.f + erff(v * 0.70710678118654752f));
                        g_hbuf[(size_t)r*1024 + cidx] = v;
                    } else {
                        v += bias[cidx] + resid[(size_t)r*256 + cidx];
                        int b = r / NTc, p = r % NTc;
                        out[((size_t)b*Cdim + cidx)*NTc + p] = v;
                    }
                }
            }
        }
    }
}

__global__ __launch_bounds__(256) void sgemm_tc(
    const float* __restrict__ A, const float* __restrict__ Bw,
    int Mrows, int Ncols, int Kdim, int mode,
    const float* __restrict__ bias, const float* __restrict__ resid,
    float* __restrict__ out)
{
    sgemm_body(A, Bw, Mrows, Ncols, Kdim, mode, bias, resid, out,
               blockIdx.x, blockIdx.y);
}

// merged Q-proj + KV-proj launch: grid (37, 12); y<4 -> Wq, y>=4 -> Wkv
__global__ __launch_bounds__(256) void sgemm_qkv(
    const float* __restrict__ qin, const float* __restrict__ Wq,
    const float* __restrict__ kin, const float* __restrict__ Wkv)
{
    if (blockIdx.y < 4)
        sgemm_body(qin, Wq, Bc*NTc, Cdim, KDc, 0, nullptr, nullptr, nullptr,
                   blockIdx.x, blockIdx.y);
    else
        sgemm_body(kin, Wkv, Bc*Nc, 2*Cdim, KDc, 1, nullptr, nullptr, nullptr,
                   blockIdx.x, blockIdx.y - 4);
}

// ---------------- fused tensor-core two-pass masked attention (R9) ---------
// no-max softmax; pass-2 exp(p) via Taylor for B segment. Single-buffered
// tiles; __launch_bounds__(256,2) pins 2 CTAs/SM (regs <= 128).
// grid: (NT/128, B*HDS), block 256
__global__ __launch_bounds__(256, 2) void attn_kernel(
    const float* __restrict__ mask, float* __restrict__ out)
{
    __shared__ __nv_bfloat16 Ks[64][40];
    __shared__ __nv_bfloat16 Vt[32][72];

    int bh = blockIdx.y;
    int b = bh >> 3, h = bh & 7;
    int m0 = blockIdx.x * 128;
    const __nv_bfloat16* Qg = g_qh + ((size_t)bh*NTc + m0)*HDc;
    const __nv_bfloat16* Kg = g_kh + (size_t)bh*Nc*HDc;
    const __nv_bfloat16* Vg = g_vt + (size_t)bh*HDc*NcP;
    const float* Mk = mask + ((size_t)bh*Nc + CLSc + m0)*Nc;

    int t = threadIdx.x;
    int wr = t >> 5, lane = t & 31;
    int qr = lane >> 2, c0 = (lane & 3) * 2;
    int r = wr*16 + qr;

    unsigned aq[2][4];
#pragma unroll
    for (int kk = 0; kk < 2; kk++) {
        aq[kk][0] = *(const unsigned*)&Qg[(size_t)r    *HDc + kk*16 + c0];
        aq[kk][1] = *(const unsigned*)&Qg[(size_t)(r+8)*HDc + kk*16 + c0];
        aq[kk][2] = *(const unsigned*)&Qg[(size_t)r    *HDc + kk*16 + c0 + 8];
        aq[kk][3] = *(const unsigned*)&Qg[(size_t)(r+8)*HDc + kk*16 + c0 + 8];
    }

    float lA[2] = {0.f, 0.f}, lB[2] = {0.f, 0.f};

    // ---------------- pass 1: segment sumexp ----------------
    for (int n0 = 0; n0 < Nc; n0 += 64) {
        __syncthreads();
        {
            int row = t >> 2, seg = t & 3;
            float4 kv = make_float4(0.f,0.f,0.f,0.f);
            if (n0 + row < Nc)
                kv = *(const float4*)&Kg[(size_t)(n0+row)*HDc + seg*8];
            *(float4*)&Ks[row][seg*8] = kv;
        }
        __syncthreads();

        float sacc[8][4];
#pragma unroll
        for (int j = 0; j < 8; j++) { sacc[j][0]=0.f; sacc[j][1]=0.f; sacc[j][2]=0.f; sacc[j][3]=0.f; }
#pragma unroll
        for (int j = 0; j < 8; j++) {
#pragma unroll
            for (int kk = 0; kk < 2; kk++) {
                unsigned bv[2];
                bv[0] = *(const unsigned*)&Ks[j*8 + qr][kk*16 + c0];
                bv[1] = *(const unsigned*)&Ks[j*8 + qr][kk*16 + c0 + 8];
                mma16816(sacc[j], aq[kk], bv);
            }
        }

        if (n0 == 0) {
#pragma unroll
            for (int j = 0; j < 8; j++)
#pragma unroll
                for (int ri = 0; ri < 2; ri++)
#pragma unroll
                    for (int e = 0; e < 2; e++) {
                        int n = j*8 + c0 + e;
                        float ex = __expf(sacc[j][ri*2+e]);
                        if (n < CLSc) lA[ri] += ex; else lB[ri] += ex;
                    }
        } else {
#pragma unroll
            for (int j = 0; j < 8; j++)
#pragma unroll
                for (int ri = 0; ri < 2; ri++)
#pragma unroll
                    for (int e = 0; e < 2; e++) {
                        int n = n0 + j*8 + c0 + e;
                        if (n < Nc) lB[ri] += __expf(sacc[j][ri*2+e]);
                    }
        }
    }

#pragma unroll
    for (int ri = 0; ri < 2; ri++) {
        lA[ri] += __shfl_xor_sync(0xffffffffu, lA[ri], 1);
        lA[ri] += __shfl_xor_sync(0xffffffffu, lA[ri], 2);
        lB[ri] += __shfl_xor_sync(0xffffffffu, lB[ri], 1);
        lB[ri] += __shfl_xor_sync(0xffffffffu, lB[ri], 2);
    }
    float ilA[2], ilB[2], den[2] = {0.f, 0.f};
#pragma unroll
    for (int ri = 0; ri < 2; ri++) { ilA[ri] = 1.f/lA[ri]; ilB[ri] = 1.f/lB[ri]; }

    float oacc[4][4];
#pragma unroll
    for (int jd = 0; jd < 4; jd++) { oacc[jd][0]=0.f; oacc[jd][1]=0.f; oacc[jd][2]=0.f; oacc[jd][3]=0.f; }

    // ---------------- pass 2 ----------------
    for (int n0 = 0; n0 < Nc; n0 += 64) {
        __syncthreads();
        {
            int row = t >> 2, seg = t & 3;
            float4 kv = make_float4(0.f,0.f,0.f,0.f);
            if (n0 + row < Nc)
                kv = *(const float4*)&Kg[(size_t)(n0+row)*HDc + seg*8];
            *(float4*)&Ks[row][seg*8] = kv;
            int d = t >> 3, vseg = t & 7;
            int nb = n0 + vseg*8;
            float4 vv = make_float4(0.f,0.f,0.f,0.f);
            if (nb + 8 <= NcP)
                vv = *(const float4*)&Vg[(size_t)d*NcP + nb];
            *(float4*)&Vt[d][vseg*8] = vv;
        }
        __syncthreads();

        float sacc[8][4];
#pragma unroll
        for (int j = 0; j < 8; j++) { sacc[j][0]=0.f; sacc[j][1]=0.f; sacc[j][2]=0.f; sacc[j][3]=0.f; }
#pragma unroll
        for (int j = 0; j < 8; j++) {
#pragma unroll
            for (int kk = 0; kk < 2; kk++) {
                unsigned bv[2];
                bv[0] = *(const unsigned*)&Ks[j*8 + qr][kk*16 + c0];
                bv[1] = *(const unsigned*)&Ks[j*8 + qr][kk*16 + c0 + 8];
                mma16816(sacc[j], aq[kk], bv);
            }
        }

#pragma unroll
        for (int j = 0; j < 8; j++) {
            int np = n0 + j*8 + c0;
            float mk[2][2] = {{0.f,0.f},{0.f,0.f}};
            if (np + 1 < Nc) {
                float2 m0v = *(const float2*)&Mk[(size_t)r    *Nc + np];
                float2 m1v = *(const float2*)&Mk[(size_t)(r+8)*Nc + np];
                mk[0][0]=m0v.x; mk[0][1]=m0v.y; mk[1][0]=m1v.x; mk[1][1]=m1v.y;
            } else if (np < Nc) {
                mk[0][0] = Mk[(size_t)r*Nc + np];
                mk[1][0] = Mk[(size_t)(r+8)*Nc + np];
            }
#pragma unroll
            for (int ri = 0; ri < 2; ri++)
#pragma unroll
                for (int e = 0; e < 2; e++) {
                    int n = np + e;
                    float w = 0.f;
                    if (n < Nc && mk[ri][e] >= MRc) {
                        float ex = __expf(sacc[j][ri*2+e]);
                        if (n < CLSc) {
                            w = __expf(ex * ilA[ri]);
                        } else {
                            float p = ex * ilB[ri];
                            w = 1.f + p*(1.f + p*(0.5f + p*(0.16666667f + p*0.04166667f)));
                        }
                    }
                    den[ri] += w;
                    sacc[j][ri*2+e] = w;
                }
        }

#pragma unroll
        for (int kk = 0; kk < 4; kk++) {
            unsigned ap[4];
            ap[0] = packbf(sacc[2*kk  ][0], sacc[2*kk  ][1]);
            ap[1] = packbf(sacc[2*kk  ][2], sacc[2*kk  ][3]);
            ap[2] = packbf(sacc[2*kk+1][0], sacc[2*kk+1][1]);
            ap[3] = packbf(sacc[2*kk+1][2], sacc[2*kk+1][3]);
#pragma unroll
            for (int jd = 0; jd < 4; jd++) {
                unsigned bv[2];
                bv[0] = *(const unsigned*)&Vt[jd*8 + qr][kk*16 + c0];
                bv[1] = *(const unsigned*)&Vt[jd*8 + qr][kk*16 + c0 + 8];
                mma16816(oacc[jd], ap, bv);
            }
        }
    }

#pragma unroll
    for (int ri = 0; ri < 2; ri++) {
        den[ri] += __shfl_xor_sync(0xffffffffu, den[ri], 1);
        den[ri] += __shfl_xor_sync(0xffffffffu, den[ri], 2);
    }
    float inv0 = 1.f/den[0], inv1 = 1.f/den[1];
#pragma unroll
    for (int jd = 0; jd < 4; jd++) {
        int col = h*HDc + jd*8 + c0;
        size_t o0 = ((size_t)b*NTc + m0 + r    )*Cdim + col;
        size_t o1 = ((size_t)b*NTc + m0 + r + 8)*Cdim + col;
        *(float2*)&out[o0] = make_float2(oacc[jd][0]*inv0, oacc[jd][1]*inv0);
        *(float2*)&out[o1] = make_float2(oacc[jd][2]*inv1, oacc[jd][3]*inv1);
    }
}

// ---------------- launch ----------------
extern "C" void kernel_launch(void* const* d_in, const int* in_sizes, int n_in,
                              void* d_out, int out_size)
{
    const float* x_query = (const float*)d_in[0];
    const float* x_key   = (const float*)d_in[1];
    const float* mask_u  = (const float*)d_in[2];
    const float* g1  = (const float*)d_in[3];
    const float* be1 = (const float*)d_in[4];
    const float* g2  = (const float*)d_in[5];
    const float* be2 = (const float*)d_in[6];
    const float* g3  = (const float*)d_in[7];
    const float* be3 = (const float*)d_in[8];
    const float* Wq  = (const float*)d_in[9];
    const float* Wkv = (const float*)d_in[10];
    const float* Wp  = (const float*)d_in[12];
    const float* bp  = (const float*)d_in[13];
    const float* W1  = (const float*)d_in[14];
    const float* bf1 = (const float*)d_in[15];
    const float* W2  = (const float*)d_in[16];
    const float* bf2 = (const float*)d_in[17];
    float* out = (float*)d_out;

    float *xqt, *qin, *kin, *xattn, *xres, *xln, *hbuf;
    cudaGetSymbolAddress((void**)&xqt,   g_xqt);
    cudaGetSymbolAddress((void**)&qin,   g_qin);
    cudaGetSymbolAddress((void**)&kin,   g_kin);
    cudaGetSymbolAddress((void**)&xattn, g_xattn);
    cudaGetSymbolAddress((void**)&xres,  g_xres);
    cudaGetSymbolAddress((void**)&xln,   g_xln);
    cudaGetSymbolAddress((void**)&hbuf,  g_hbuf);

    // 1) fused LNs (x_key rows + x_query transpose-LN)
    ln_fused_kernel<<<Bc*Nc + Bc*(NTc/32), 256>>>(
        x_query, g1, be1, xqt, qin, x_key, g2, be2, kin);
    // 2) merged Q + KV projection
    sgemm_qkv<<<dim3(37, 12), 256>>>(qin, Wq, kin, Wkv);
    // 3) attention
    attn_kernel<<<dim3(NTc/128, Bc*HDSc), 256>>>(mask_u, xattn);
    // 4) proj + residual
    sgemm_tc<<<dim3((Bc*NTc)/128, Cdim/64), 256>>>(xattn, Wp, Bc*NTc, Cdim, Cdim, 2, bp, xqt, nullptr);
    // 5) LN for FFN
    ln_row_kernel<<<Bc*NTc, 256>>>(xres, g3, be3, xln);
    // 6) FFN1 + GELU
    sgemm_tc<<<dim3((Bc*NTc)/128, (4*Cdim)/64), 256>>>(xln, W1, Bc*NTc, 4*Cdim, Cdim, 3, bf1, nullptr, nullptr);
    // 7) FFN2 + residual + transpose out
    sgemm_tc<<<dim3((Bc*NTc)/128, Cdim/64), 256>>>(hbuf, W2, Bc*NTc, Cdim, 4*Cdim, 4, bf2, xres, out);
}

// round 15
// speedup vs baseline: 1.1600x; 1.0381x over previous
#include <cuda_runtime.h>
#include <cuda_bf16.h>
#include <math.h>

#define Bc 2
#define Cdim 256
#define NTc 2304
#define KDc 256
#define CLSc 20
#define Nc 2324
#define NcP 2336
#define HDSc 8
#define HDc 32
#define SCALEc 0.17677669529663687f
#define EPSc 1e-5f
#define MRc 0.3f

// ---------------- device scratch ----------------
__device__ float g_xqt[Bc*NTc*Cdim];
__device__ float g_qin[Bc*NTc*Cdim];
__device__ float g_kin[Bc*Nc*KDc];
__device__ __nv_bfloat16 g_qh[Bc*HDSc*NTc*HDc];
__device__ __nv_bfloat16 g_kh[Bc*HDSc*Nc*HDc];
__device__ __nv_bfloat16 g_vt[Bc*HDSc*HDc*NcP];
__device__ float g_xattn[Bc*NTc*Cdim];
__device__ float g_xres [Bc*NTc*Cdim];
__device__ float g_xln  [Bc*NTc*Cdim];
__device__ float g_hbuf [Bc*NTc*4*Cdim];

__device__ __forceinline__ void mma16816(float* c, const unsigned* a, const unsigned* b){
    asm volatile(
        "mma.sync.aligned.m16n8k16.row.col.f32.bf16.bf16.f32 "
        "{%0,%1,%2,%3}, {%4,%5,%6,%7}, {%8,%9}, {%0,%1,%2,%3};\n"
        : "+f"(c[0]), "+f"(c[1]), "+f"(c[2]), "+f"(c[3])
        : "r"(a[0]), "r"(a[1]), "r"(a[2]), "r"(a[3]), "r"(b[0]), "r"(b[1]));
}
__device__ __forceinline__ void mma1688_tf32(float* c, const unsigned* a, const unsigned* b){
    asm volatile(
        "mma.sync.aligned.m16n8k8.row.col.f32.tf32.tf32.f32 "
        "{%0,%1,%2,%3}, {%4,%5,%6,%7}, {%8,%9}, {%0,%1,%2,%3};\n"
        : "+f"(c[0]), "+f"(c[1]), "+f"(c[2]), "+f"(c[3])
        : "r"(a[0]), "r"(a[1]), "r"(a[2]), "r"(a[3]), "r"(b[0]), "r"(b[1]));
}
__device__ __forceinline__ unsigned f2tf32(float x){
    unsigned r;
    asm("cvt.rna.tf32.f32 %0, %1;" : "=r"(r) : "f"(x));
    return r;
}
__device__ __forceinline__ unsigned packbf(float lo, float hi){
    __nv_bfloat162 t = __floats2bfloat162_rn(lo, hi);
    return *(unsigned*)&t;
}
__device__ __forceinline__ void cp16(unsigned dst, const void* src, int srcbytes){
    asm volatile("cp.async.ca.shared.global [%0], [%1], 16, %2;\n"
                 :: "r"(dst), "l"(src), "r"(srcbytes));
}
#define CP_COMMIT()  asm volatile("cp.async.commit_group;\n")
#define CP_WAIT0()   asm volatile("cp.async.wait_group 0;\n")

// ---------------- fused LN: x_key rows + x_query transpose-LN --------------
__global__ __launch_bounds__(256) void ln_fused_kernel(
    const float* __restrict__ xq, const float* __restrict__ g1,
    const float* __restrict__ be1, float* __restrict__ out_raw,
    float* __restrict__ out_ln,
    const float* __restrict__ xk, const float* __restrict__ g2,
    const float* __restrict__ be2, float* __restrict__ kin)
{
    __shared__ float tile[256][33];
    __shared__ float redS[8][32], redQ[8][32];
    __shared__ float s_mean[32], s_rstd[32];
    int t = threadIdx.x;
    if (blockIdx.x < Bc*Nc) {
        int r = blockIdx.x;
        float v = xk[(size_t)r*256 + t];
        float s = v, q = v*v;
#pragma unroll
        for (int off = 16; off >= 1; off >>= 1) {
            s += __shfl_xor_sync(0xffffffffu, s, off);
            q += __shfl_xor_sync(0xffffffffu, q, off);
        }
        int warp = t >> 5, lane = t & 31;
        if (lane == 0) { redS[0][warp] = s; redQ[0][warp] = q; }
        __syncthreads();
        if (t == 0) {
            float S = 0.f, Q = 0.f;
#pragma unroll
            for (int i = 0; i < 8; i++) { S += redS[0][i]; Q += redQ[0][i]; }
            float m = S * (1.f/256.f);
            float var = Q * (1.f/256.f) - m*m;
            s_mean[0] = m;
            s_rstd[0] = rsqrtf(var + EPSc);
        }
        __syncthreads();
        kin[(size_t)r*256 + t] = (v - s_mean[0]) * s_rstd[0] * g2[t] + be2[t];
    } else {
        int bi = blockIdx.x - Bc*Nc;
        int b = bi / (NTc/32);
        int p0 = (bi % (NTc/32)) * 32;
        int pl = t & 31, grp = t >> 5;
        const float* src = xq + (size_t)b*Cdim*NTc + p0 + pl;
#pragma unroll
        for (int cc = 0; cc < 32; cc++) {
            int c = cc*8 + grp;
            tile[c][pl] = src[(size_t)c*NTc];
        }
        __syncthreads();
        float s = 0.f, q = 0.f;
#pragma unroll
        for (int j = 0; j < 32; j++) {
            float v = tile[grp*32 + j][pl];
            s += v; q += v*v;
        }
        redS[grp][pl] = s; redQ[grp][pl] = q;
        __syncthreads();
        if (grp == 0) {
            float S = 0.f, Q = 0.f;
#pragma unroll
            for (int i = 0; i < 8; i++) { S += redS[i][pl]; Q += redQ[i][pl]; }
            float m = S * (1.f/256.f);
            float var = Q * (1.f/256.f) - m*m;
            s_mean[pl] = m;
            s_rstd[pl] = rsqrtf(var + EPSc);
        }
        __syncthreads();
        float gg = g1[t], bb = be1[t];
        for (int p = 0; p < 32; p++) {
            float v = tile[t][p];
            size_t o = ((size_t)b*NTc + p0 + p)*Cdim + t;
            out_raw[o] = v;
            out_ln[o]  = (v - s_mean[p]) * s_rstd[p] * gg + bb;
        }
    }
}

// ---------------- row LN (standalone, for xres) ----------------
__global__ __launch_bounds__(256) void ln_row_kernel(
    const float* __restrict__ x, const float* __restrict__ g,
    const float* __restrict__ be, float* __restrict__ y)
{
    int r = blockIdx.x;
    int t = threadIdx.x;
    float v = x[(size_t)r*256 + t];
    float s = v, q = v*v;
#pragma unroll
    for (int off = 16; off >= 1; off >>= 1) {
        s += __shfl_xor_sync(0xffffffffu, s, off);
        q += __shfl_xor_sync(0xffffffffu, q, off);
    }
    __shared__ float ss[8], sq[8];
    __shared__ float s_mean, s_rstd;
    int warp = t >> 5, lane = t & 31;
    if (lane == 0) { ss[warp] = s; sq[warp] = q; }
    __syncthreads();
    if (t == 0) {
        float S = 0.f, Q = 0.f;
#pragma unroll
        for (int i = 0; i < 8; i++) { S += ss[i]; Q += sq[i]; }
        float m = S * (1.f/256.f);
        float var = Q * (1.f/256.f) - m*m;
        s_mean = m;
        s_rstd = rsqrtf(var + EPSc);
    }
    __syncthreads();
    y[(size_t)r*256 + t] = (v - s_mean) * s_rstd * g[t] + be[t];
}

// ---------------- TF32 GEMM body, BM=128 BN=64 BK=32, 2-stage --------------
__device__ __forceinline__ void sgemm_body(
    const float* __restrict__ A, const float* __restrict__ Bw,
    int Mrows, int Ncols, int Kdim, int mode,
    const float* __restrict__ bias, const float* __restrict__ resid,
    float* __restrict__ out, int mblk, int nblk)
{
    __shared__ unsigned As[2][128][36];
    __shared__ unsigned Bs[2][32][68];

    int m0 = mblk * 128, n0 = nblk * 64;
    int t = threadIdx.x;
    int wid = t >> 5, lane = t & 31;
    int wm = wid & 3, wn = wid >> 2;
    int qr = lane >> 2, tig = lane & 3;

    float c[2][4][4];
#pragma unroll
    for (int mt = 0; mt < 2; mt++)
#pragma unroll
        for (int nt = 0; nt < 4; nt++)
#pragma unroll
            for (int e = 0; e < 4; e++) c[mt][nt][e] = 0.f;

    int ar = t >> 3, ac4 = (t & 7) * 4;
    int br = t >> 4, bc4 = (t & 15) * 4;
    int nit = Kdim >> 5;

    float4 aReg[4], bReg[2];
#pragma unroll
    for (int i = 0; i < 4; i++) {
        int row = ar + i*32;
        aReg[i] = make_float4(0.f,0.f,0.f,0.f);
        if (m0 + row < Mrows)
            aReg[i] = *(const float4*)&A[(size_t)(m0+row)*Kdim + ac4];
    }
#pragma unroll
    for (int i = 0; i < 2; i++)
        bReg[i] = *(const float4*)&Bw[(size_t)(br + i*16)*Ncols + n0 + bc4];
#pragma unroll
    for (int i = 0; i < 4; i++) {
        int row = ar + i*32;
        As[0][row][ac4+0] = f2tf32(aReg[i].x); As[0][row][ac4+1] = f2tf32(aReg[i].y);
        As[0][row][ac4+2] = f2tf32(aReg[i].z); As[0][row][ac4+3] = f2tf32(aReg[i].w);
    }
#pragma unroll
    for (int i = 0; i < 2; i++) {
        int row = br + i*16;
        Bs[0][row][bc4+0] = f2tf32(bReg[i].x); Bs[0][row][bc4+1] = f2tf32(bReg[i].y);
        Bs[0][row][bc4+2] = f2tf32(bReg[i].z); Bs[0][row][bc4+3] = f2tf32(bReg[i].w);
    }

    for (int it = 0; it < nit; it++) {
        __syncthreads();
        int cur = it & 1, nxt = cur ^ 1;
        if (it + 1 < nit) {
            int k0 = (it + 1) << 5;
#pragma unroll
            for (int i = 0; i < 4; i++) {
                int row = ar + i*32;
                aReg[i] = make_float4(0.f,0.f,0.f,0.f);
                if (m0 + row < Mrows)
                    aReg[i] = *(const float4*)&A[(size_t)(m0+row)*Kdim + k0 + ac4];
            }
#pragma unroll
            for (int i = 0; i < 2; i++)
                bReg[i] = *(const float4*)&Bw[(size_t)(k0 + br + i*16)*Ncols + n0 + bc4];
        }

#pragma unroll
        for (int kk = 0; kk < 32; kk += 8) {
            unsigned afr[2][4], bfr[4][2];
#pragma unroll
            for (int mt = 0; mt < 2; mt++) {
                int rb = wm*32 + mt*16;
                afr[mt][0] = As[cur][rb + qr    ][kk + tig];
                afr[mt][1] = As[cur][rb + qr + 8][kk + tig];
                afr[mt][2] = As[cur][rb + qr    ][kk + tig + 4];
                afr[mt][3] = As[cur][rb + qr + 8][kk + tig + 4];
            }
#pragma unroll
            for (int nt = 0; nt < 4; nt++) {
                int cb = wn*32 + nt*8 + qr;
                bfr[nt][0] = Bs[cur][kk + tig    ][cb];
                bfr[nt][1] = Bs[cur][kk + tig + 4][cb];
            }
#pragma unroll
            for (int mt = 0; mt < 2; mt++)
#pragma unroll
                for (int nt = 0; nt < 4; nt++)
                    mma1688_tf32(c[mt][nt], afr[mt], bfr[nt]);
        }

        if (it + 1 < nit) {
#pragma unroll
            for (int i = 0; i < 4; i++) {
                int row = ar + i*32;
                As[nxt][row][ac4+0] = f2tf32(aReg[i].x); As[nxt][row][ac4+1] = f2tf32(aReg[i].y);
                As[nxt][row][ac4+2] = f2tf32(aReg[i].z); As[nxt][row][ac4+3] = f2tf32(aReg[i].w);
            }
#pragma unroll
            for (int i = 0; i < 2; i++) {
                int row = br + i*16;
                Bs[nxt][row][bc4+0] = f2tf32(bReg[i].x); Bs[nxt][row][bc4+1] = f2tf32(bReg[i].y);
                Bs[nxt][row][bc4+2] = f2tf32(bReg[i].z); Bs[nxt][row][bc4+3] = f2tf32(bReg[i].w);
            }
        }
    }

#pragma unroll
    for (int mt = 0; mt < 2; mt++) {
#pragma unroll
        for (int ri = 0; ri < 2; ri++) {
            int r = m0 + wm*32 + mt*16 + qr + ri*8;
            if (r >= Mrows) continue;
#pragma unroll
            for (int nt = 0; nt < 4; nt++) {
#pragma unroll
                for (int e = 0; e < 2; e++) {
                    int cidx = n0 + wn*32 + nt*8 + tig*2 + e;
                    float v = c[mt][nt][ri*2 + e];
                    if (mode == 0) {
                        int b = r / NTc, ii = r % NTc;
                        int h = cidx >> 5, d = cidx & 31;
                        g_qh[(((size_t)b*HDSc + h)*NTc + ii)*HDc + d] = __float2bfloat16(v * SCALEc);
                    } else if (mode == 1) {
                        int b = r / Nc, nn = r % Nc;
                        int two = cidx >> 8; int c2 = cidx & 255;
                        int h = c2 >> 5, d = c2 & 31;
                        if (two)
                            g_vt[(((size_t)b*HDSc + h)*HDc + d)*NcP + nn] = __float2bfloat16(v);
                        else
                            g_kh[(((size_t)b*HDSc + h)*Nc + nn)*HDc + d] = __float2bfloat16(v);
                    } else if (mode == 2) {
                        v += bias[cidx] + resid[(size_t)r*256 + cidx];
                        g_xres[(size_t)r*256 + cidx] = v;
                    } else if (mode == 3) {
                        v += bias[cidx];
                        v = 0.5f * v * (1.f + erff(v * 0.70710678118654752f));
                        g_hbuf[(size_t)r*1024 + cidx] = v;
                    } else {
                        v += bias[cidx] + resid[(size_t)r*256 + cidx];
                        int b = r / NTc, p = r % NTc;
                        out[((size_t)b*Cdim + cidx)*NTc + p] = v;
                    }
                }
            }
        }
    }
}

__global__ __launch_bounds__(256) void sgemm_tc(
    const float* __restrict__ A, const float* __restrict__ Bw,
    int Mrows, int Ncols, int Kdim, int mode,
    const float* __restrict__ bias, const float* __restrict__ resid,
    float* __restrict__ out)
{
    sgemm_body(A, Bw, Mrows, Ncols, Kdim, mode, bias, resid, out,
               blockIdx.x, blockIdx.y);
}

__global__ __launch_bounds__(256) void sgemm_qkv(
    const float* __restrict__ qin, const float* __restrict__ Wq,
    const float* __restrict__ kin, const float* __restrict__ Wkv)
{
    if (blockIdx.y < 4)
        sgemm_body(qin, Wq, Bc*NTc, Cdim, KDc, 0, nullptr, nullptr, nullptr,
                   blockIdx.x, blockIdx.y);
    else
        sgemm_body(kin, Wkv, Bc*Nc, 2*Cdim, KDc, 1, nullptr, nullptr, nullptr,
                   blockIdx.x, blockIdx.y - 4);
}

// ---------------- two-pass attention, cp.async double-buffered -------------
// Same arithmetic as R9 (no-max softmax, pass-2 Taylor for B). cp.async
// prefetch: zero register staging, 1 sync per tile.
// grid: (NT/128, B*HDS), block 256
__global__ __launch_bounds__(256, 2) void attn_kernel(
    const float* __restrict__ mask, float* __restrict__ out)
{
    __shared__ __nv_bfloat16 Ks[2][64][40];
    __shared__ __nv_bfloat16 Vt[2][32][72];

    int bh = blockIdx.y;
    int b = bh >> 3, h = bh & 7;
    int m0 = blockIdx.x * 128;
    const __nv_bfloat16* Qg = g_qh + ((size_t)bh*NTc + m0)*HDc;
    const __nv_bfloat16* Kg = g_kh + (size_t)bh*Nc*HDc;
    const __nv_bfloat16* Vg = g_vt + (size_t)bh*HDc*NcP;
    const float* Mk = mask + ((size_t)bh*Nc + CLSc + m0)*Nc;

    int t = threadIdx.x;
    int wr = t >> 5, lane = t & 31;
    int qr = lane >> 2, c0 = (lane & 3) * 2;
    int r = wr*16 + qr;
    int krow = t >> 2, kseg = t & 3;   // K loader: 64 rows x 4 granules of 16B
    int vd = t >> 3, vseg = t & 7;     // V loader: 32 rows x 8 granules of 16B

    unsigned aq[2][4];
#pragma unroll
    for (int kk = 0; kk < 2; kk++) {
        aq[kk][0] = *(const unsigned*)&Qg[(size_t)r    *HDc + kk*16 + c0];
        aq[kk][1] = *(const unsigned*)&Qg[(size_t)(r+8)*HDc + kk*16 + c0];
        aq[kk][2] = *(const unsigned*)&Qg[(size_t)r    *HDc + kk*16 + c0 + 8];
        aq[kk][3] = *(const unsigned*)&Qg[(size_t)(r+8)*HDc + kk*16 + c0 + 8];
    }

    const int NTILES = 37;   // 37*64 = 2368 >= Nc
    float lA[2] = {0.f, 0.f}, lB[2] = {0.f, 0.f};

    // ---------------- pass 1: segment sumexp (K only) ----------------
    cp16((unsigned)__cvta_generic_to_shared(&Ks[0][krow][kseg*8]),
         &Kg[(size_t)krow*HDc + kseg*8], krow < Nc ? 16 : 0);
    CP_COMMIT();

    for (int it = 0; it < NTILES; it++) {
        int cur = it & 1, nxt = cur ^ 1;
        int n0 = it * 64;
        CP_WAIT0();
        __syncthreads();
        if (it + 1 < NTILES) {
            int nn0 = n0 + 64;
            cp16((unsigned)__cvta_generic_to_shared(&Ks[nxt][krow][kseg*8]),
                 &Kg[(size_t)(nn0+krow)*HDc + kseg*8], (nn0+krow) < Nc ? 16 : 0);
            CP_COMMIT();
        }

        float sacc[8][4];
#pragma unroll
        for (int j = 0; j < 8; j++) { sacc[j][0]=0.f; sacc[j][1]=0.f; sacc[j][2]=0.f; sacc[j][3]=0.f; }
#pragma unroll
        for (int j = 0; j < 8; j++) {
#pragma unroll
            for (int kk = 0; kk < 2; kk++) {
                unsigned bv[2];
                bv[0] = *(const unsigned*)&Ks[cur][j*8 + qr][kk*16 + c0];
                bv[1] = *(const unsigned*)&Ks[cur][j*8 + qr][kk*16 + c0 + 8];
                mma16816(sacc[j], aq[kk], bv);
            }
        }

        if (it == 0) {
#pragma unroll
            for (int j = 0; j < 8; j++)
#pragma unroll
                for (int ri = 0; ri < 2; ri++)
#pragma unroll
                    for (int e = 0; e < 2; e++) {
                        int n = j*8 + c0 + e;
                        float ex = __expf(sacc[j][ri*2+e]);
                        if (n < CLSc) lA[ri] += ex; else lB[ri] += ex;
                    }
        } else {
#pragma unroll
            for (int j = 0; j < 8; j++)
#pragma unroll
                for (int ri = 0; ri < 2; ri++)
#pragma unroll
                    for (int e = 0; e < 2; e++) {
                        int n = n0 + j*8 + c0 + e;
                        if (n < Nc) lB[ri] += __expf(sacc[j][ri*2+e]);
                    }
        }
    }

#pragma unroll
    for (int ri = 0; ri < 2; ri++) {
        lA[ri] += __shfl_xor_sync(0xffffffffu, lA[ri], 1);
        lA[ri] += __shfl_xor_sync(0xffffffffu, lA[ri], 2);
        lB[ri] += __shfl_xor_sync(0xffffffffu, lB[ri], 1);
        lB[ri] += __shfl_xor_sync(0xffffffffu, lB[ri], 2);
    }
    float ilA[2], ilB[2], den[2] = {0.f, 0.f};
#pragma unroll
    for (int ri = 0; ri < 2; ri++) { ilA[ri] = 1.f/lA[ri]; ilB[ri] = 1.f/lB[ri]; }

    float oacc[4][4];
#pragma unroll
    for (int jd = 0; jd < 4; jd++) { oacc[jd][0]=0.f; oacc[jd][1]=0.f; oacc[jd][2]=0.f; oacc[jd][3]=0.f; }

    // ---------------- pass 2 (K+V) ----------------
    __syncthreads();   // pass-1 readers of buffer 0 done before reload
    cp16((unsigned)__cvta_generic_to_shared(&Ks[0][krow][kseg*8]),
         &Kg[(size_t)krow*HDc + kseg*8], krow < Nc ? 16 : 0);
    cp16((unsigned)__cvta_generic_to_shared(&Vt[0][vd][vseg*8]),
         &Vg[(size_t)vd*NcP + vseg*8], (vseg*8 + 8) <= NcP ? 16 : 0);
    CP_COMMIT();

    for (int it = 0; it < NTILES; it++) {
        int cur = it & 1, nxt = cur ^ 1;
        int n0 = it * 64;
        CP_WAIT0();
        __syncthreads();
        if (it + 1 < NTILES) {
            int nn0 = n0 + 64;
            cp16((unsigned)__cvta_generic_to_shared(&Ks[nxt][krow][kseg*8]),
                 &Kg[(size_t)(nn0+krow)*HDc + kseg*8], (nn0+krow) < Nc ? 16 : 0);
            cp16((unsigned)__cvta_generic_to_shared(&Vt[nxt][vd][vseg*8]),
                 &Vg[(size_t)vd*NcP + nn0 + vseg*8], (nn0 + vseg*8 + 8) <= NcP ? 16 : 0);
            CP_COMMIT();
        }

        float sacc[8][4];
#pragma unroll
        for (int j = 0; j < 8; j++) { sacc[j][0]=0.f; sacc[j][1]=0.f; sacc[j][2]=0.f; sacc[j][3]=0.f; }
#pragma unroll
        for (int j = 0; j < 8; j++) {
#pragma unroll
            for (int kk = 0; kk < 2; kk++) {
                unsigned bv[2];
                bv[0] = *(const unsigned*)&Ks[cur][j*8 + qr][kk*16 + c0];
                bv[1] = *(const unsigned*)&Ks[cur][j*8 + qr][kk*16 + c0 + 8];
                mma16816(sacc[j], aq[kk], bv);
            }
        }

#pragma unroll
        for (int j = 0; j < 8; j++) {
            int np = n0 + j*8 + c0;
            float mk[2][2] = {{0.f,0.f},{0.f,0.f}};
            if (np + 1 < Nc) {
                float2 m0v = *(const float2*)&Mk[(size_t)r    *Nc + np];
                float2 m1v = *(const float2*)&Mk[(size_t)(r+8)*Nc + np];
                mk[0][0]=m0v.x; mk[0][1]=m0v.y; mk[1][0]=m1v.x; mk[1][1]=m1v.y;
            } else if (np < Nc) {
                mk[0][0] = Mk[(size_t)r*Nc + np];
                mk[1][0] = Mk[(size_t)(r+8)*Nc + np];
            }
#pragma unroll
            for (int ri = 0; ri < 2; ri++)
#pragma unroll
                for (int e = 0; e < 2; e++) {
                    int n = np + e;
                    float w = 0.f;
                    if (n < Nc && mk[ri][e] >= MRc) {
                        float ex = __expf(sacc[j][ri*2+e]);
                        if (n < CLSc) {
                            w = __expf(ex * ilA[ri]);
                        } else {
                            float p = ex * ilB[ri];
                            w = 1.f + p*(1.f + p*(0.5f + p*(0.16666667f + p*0.04166667f)));
                        }
                    }
                    den[ri] += w;
                    sacc[j][ri*2+e] = w;
                }
        }

#pragma unroll
        for (int kk = 0; kk < 4; kk++) {
            unsigned ap[4];
            ap[0] = packbf(sacc[2*kk  ][0], sacc[2*kk  ][1]);
            ap[1] = packbf(sacc[2*kk  ][2], sacc[2*kk  ][3]);
            ap[2] = packbf(sacc[2*kk+1][0], sacc[2*kk+1][1]);
            ap[3] = packbf(sacc[2*kk+1][2], sacc[2*kk+1][3]);
#pragma unroll
            for (int jd = 0; jd < 4; jd++) {
                unsigned bv[2];
                bv[0] = *(const unsigned*)&Vt[cur][jd*8 + qr][kk*16 + c0];
                bv[1] = *(const unsigned*)&Vt[cur][jd*8 + qr][kk*16 + c0 + 8];
                mma16816(oacc[jd], ap, bv);
            }
        }
    }

#pragma unroll
    for (int ri = 0; ri < 2; ri++) {
        den[ri] += __shfl_xor_sync(0xffffffffu, den[ri], 1);
        den[ri] += __shfl_xor_sync(0xffffffffu, den[ri], 2);
    }
    float inv0 = 1.f/den[0], inv1 = 1.f/den[1];
#pragma unroll
    for (int jd = 0; jd < 4; jd++) {
        int col = h*HDc + jd*8 + c0;
        size_t o0 = ((size_t)b*NTc + m0 + r    )*Cdim + col;
        size_t o1 = ((size_t)b*NTc + m0 + r + 8)*Cdim + col;
        *(float2*)&out[o0] = make_float2(oacc[jd][0]*inv0, oacc[jd][1]*inv0);
        *(float2*)&out[o1] = make_float2(oacc[jd][2]*inv1, oacc[jd][3]*inv1);
    }
}

// ---------------- launch ----------------
extern "C" void kernel_launch(void* const* d_in, const int* in_sizes, int n_in,
                              void* d_out, int out_size)
{
    const float* x_query = (const float*)d_in[0];
    const float* x_key   = (const float*)d_in[1];
    const float* mask_u  = (const float*)d_in[2];
    const float* g1  = (const float*)d_in[3];
    const float* be1 = (const float*)d_in[4];
    const float* g2  = (const float*)d_in[5];
    const float* be2 = (const float*)d_in[6];
    const float* g3  = (const float*)d_in[7];
    const float* be3 = (const float*)d_in[8];
    const float* Wq  = (const float*)d_in[9];
    const float* Wkv = (const float*)d_in[10];
    const float* Wp  = (const float*)d_in[12];
    const float* bp  = (const float*)d_in[13];
    const float* W1  = (const float*)d_in[14];
    const float* bf1 = (const float*)d_in[15];
    const float* W2  = (const float*)d_in[16];
    const float* bf2 = (const float*)d_in[17];
    float* out = (float*)d_out;

    float *xqt, *qin, *kin, *xattn, *xres, *xln, *hbuf;
    cudaGetSymbolAddress((void**)&xqt,   g_xqt);
    cudaGetSymbolAddress((void**)&qin,   g_qin);
    cudaGetSymbolAddress((void**)&kin,   g_kin);
    cudaGetSymbolAddress((void**)&xattn, g_xattn);
    cudaGetSymbolAddress((void**)&xres,  g_xres);
    cudaGetSymbolAddress((void**)&xln,   g_xln);
    cudaGetSymbolAddress((void**)&hbuf,  g_hbuf);

    ln_fused_kernel<<<Bc*Nc + Bc*(NTc/32), 256>>>(
        x_query, g1, be1, xqt, qin, x_key, g2, be2, kin);
    sgemm_qkv<<<dim3(37, 12), 256>>>(qin, Wq, kin, Wkv);
    attn_kernel<<<dim3(NTc/128, Bc*HDSc), 256>>>(mask_u, xattn);
    sgemm_tc<<<dim3((Bc*NTc)/128, Cdim/64), 256>>>(xattn, Wp, Bc*NTc, Cdim, Cdim, 2, bp, xqt, nullptr);
    ln_row_kernel<<<Bc*NTc, 256>>>(xres, g3, be3, xln);
    sgemm_tc<<<dim3((Bc*NTc)/128, (4*Cdim)/64), 256>>>(xln, W1, Bc*NTc, 4*Cdim, Cdim, 3, bf1, nullptr, nullptr);
    sgemm_tc<<<dim3((Bc*NTc)/128, Cdim/64), 256>>>(hbuf, W2, Bc*NTc, Cdim, 4*Cdim, 4, bf2, xres, out);
}